// round 1
// baseline (speedup 1.0000x reference)
#include <cuda_runtime.h>
#include <cstdint>

// Problem constants
#define NN 50000
#define EE 400000
#define K1 4
#define DD 1280
#define HH 256
#define NJ 1024   // K1 * HH

// Scratch (device globals — no allocations allowed)
__device__ float g_Y[(size_t)NN * NJ];      // 204.8 MB: Y = X @ W_all
__device__ float g_Wall[DD * NJ];           // 5 MB: repacked weights [D, K1*H]

// ---------------------------------------------------------------------------
// Repack W [K1, D, H] (row-major) -> W_all [D, K1*H]
// ---------------------------------------------------------------------------
__global__ void repack_w_kernel(const float* __restrict__ W) {
    int idx = blockIdx.x * blockDim.x + threadIdx.x;
    if (idx >= K1 * DD * HH) return;
    int h = idx % HH;
    int d = (idx / HH) % DD;
    int k = idx / (HH * DD);
    g_Wall[d * NJ + k * HH + h] = W[idx];
}

// ---------------------------------------------------------------------------
// SGEMM: g_Y[NN x NJ] = X[NN x DD] @ g_Wall[DD x NJ]  (fp32, tiled SIMT)
// 128x128 block tile, BK=8, 256 threads, 8x8 per-thread micro-tile.
// ---------------------------------------------------------------------------
#define BM 128
#define BN 128
#define BK 8
#define TM 8
#define TN 8

__global__ __launch_bounds__(256, 2) void sgemm_kernel(const float* __restrict__ A) {
    __shared__ float As[BK][BM];   // transposed A tile
    __shared__ float Bs[BK][BN];

    const int tid = threadIdx.x;
    const int m0 = blockIdx.y * BM;
    const int n0 = blockIdx.x * BN;

    // Global->shared load mapping (float4 per thread per tile)
    const int a_row  = tid >> 1;          // 0..127
    const int a_col4 = (tid & 1) * 4;     // 0 or 4
    const int b_row  = tid >> 5;          // 0..7
    const int b_col4 = (tid & 31) * 4;    // 0..124

    const int tx = tid & 15;              // 16 threads in N
    const int ty = tid >> 4;              // 16 threads in M

    float acc[TM][TN];
    #pragma unroll
    for (int i = 0; i < TM; i++)
        #pragma unroll
        for (int j = 0; j < TN; j++) acc[i][j] = 0.0f;

    for (int k0 = 0; k0 < DD; k0 += BK) {
        // Load A tile (guard M edge), transpose into As
        float4 av = make_float4(0.f, 0.f, 0.f, 0.f);
        int gm = m0 + a_row;
        if (gm < NN)
            av = *reinterpret_cast<const float4*>(A + (size_t)gm * DD + k0 + a_col4);
        As[a_col4 + 0][a_row] = av.x;
        As[a_col4 + 1][a_row] = av.y;
        As[a_col4 + 2][a_row] = av.z;
        As[a_col4 + 3][a_row] = av.w;

        // Load B tile (NJ=1024 divisible by BN, DD divisible by BK: no guards)
        float4 bv = *reinterpret_cast<const float4*>(
            g_Wall + (size_t)(k0 + b_row) * NJ + n0 + b_col4);
        *reinterpret_cast<float4*>(&Bs[b_row][b_col4]) = bv;

        __syncthreads();

        #pragma unroll
        for (int kk = 0; kk < BK; kk++) {
            float ra[TM], rb[TN];
            // vectorized shared loads
            float4 ra0 = *reinterpret_cast<const float4*>(&As[kk][ty * TM]);
            float4 ra1 = *reinterpret_cast<const float4*>(&As[kk][ty * TM + 4]);
            float4 rb0 = *reinterpret_cast<const float4*>(&Bs[kk][tx * TN]);
            float4 rb1 = *reinterpret_cast<const float4*>(&Bs[kk][tx * TN + 4]);
            ra[0]=ra0.x; ra[1]=ra0.y; ra[2]=ra0.z; ra[3]=ra0.w;
            ra[4]=ra1.x; ra[5]=ra1.y; ra[6]=ra1.z; ra[7]=ra1.w;
            rb[0]=rb0.x; rb[1]=rb0.y; rb[2]=rb0.z; rb[3]=rb0.w;
            rb[4]=rb1.x; rb[5]=rb1.y; rb[6]=rb1.z; rb[7]=rb1.w;
            #pragma unroll
            for (int i = 0; i < TM; i++)
                #pragma unroll
                for (int j = 0; j < TN; j++)
                    acc[i][j] = fmaf(ra[i], rb[j], acc[i][j]);
        }
        __syncthreads();
    }

    // Store (guard M edge)
    #pragma unroll
    for (int i = 0; i < TM; i++) {
        int gm = m0 + ty * TM + i;
        if (gm >= NN) break;
        float* crow = g_Y + (size_t)gm * NJ + n0 + tx * TN;
        *reinterpret_cast<float4*>(crow + 0) =
            make_float4(acc[i][0], acc[i][1], acc[i][2], acc[i][3]);
        *reinterpret_cast<float4*>(crow + 4) =
            make_float4(acc[i][4], acc[i][5], acc[i][6], acc[i][7]);
    }
}

// ---------------------------------------------------------------------------
// Init out[n,h] = sum_k b[k,h]   (out poisoned to 0xAA by harness)
// ---------------------------------------------------------------------------
__global__ void bias_init_kernel(const float* __restrict__ b, float* __restrict__ out) {
    int i = blockIdx.x * blockDim.x + threadIdx.x;   // over N*H/4 float4s
    if (i >= NN * HH / 4) return;
    int h4 = i & 63;                                  // float4 index within row
    const float4* b4 = reinterpret_cast<const float4*>(b);
    float4 s0 = b4[0 * 64 + h4];
    float4 s1 = b4[1 * 64 + h4];
    float4 s2 = b4[2 * 64 + h4];
    float4 s3 = b4[3 * 64 + h4];
    float4 s = make_float4(s0.x + s1.x + s2.x + s3.x,
                           s0.y + s1.y + s2.y + s3.y,
                           s0.z + s1.z + s2.z + s3.z,
                           s0.w + s1.w + s2.w + s3.w);
    reinterpret_cast<float4*>(out)[i] = s;
}

// ---------------------------------------------------------------------------
// SpMM scatter: for each hop k, edge e:
//   out[rows[k,e], :] += vals[k,e] * Y[cols[k,e], k*H : (k+1)*H]
// One warp per edge; 2 float4 per lane; vectorized global reductions.
// ---------------------------------------------------------------------------
__global__ void spmm_kernel(const int* __restrict__ rows,
                            const int* __restrict__ cols,
                            const float* __restrict__ vals,
                            float* __restrict__ out) {
    int gw = (int)((blockIdx.x * (size_t)blockDim.x + threadIdx.x) >> 5);
    int lane = threadIdx.x & 31;
    if (gw >= K1 * EE) return;

    int k = gw / EE;
    int r = rows[gw];
    int c = cols[gw];
    float v = vals[gw];

    const float4* yp = reinterpret_cast<const float4*>(
        g_Y + (size_t)c * NJ + k * HH);
    float* op = out + (size_t)r * HH;

    float4 y0 = yp[lane];
    float4 y1 = yp[lane + 32];

    float* a0 = op + lane * 4;
    float* a1 = op + (lane + 32) * 4;
    asm volatile("red.global.add.v4.f32 [%0], {%1,%2,%3,%4};"
                 :: "l"(a0), "f"(v * y0.x), "f"(v * y0.y), "f"(v * y0.z), "f"(v * y0.w)
                 : "memory");
    asm volatile("red.global.add.v4.f32 [%0], {%1,%2,%3,%4};"
                 :: "l"(a1), "f"(v * y1.x), "f"(v * y1.y), "f"(v * y1.z), "f"(v * y1.w)
                 : "memory");
}

// ---------------------------------------------------------------------------
// PReLU epilogue
// ---------------------------------------------------------------------------
__global__ void prelu_kernel(float* __restrict__ out, const float* __restrict__ alpha_p) {
    int i = blockIdx.x * blockDim.x + threadIdx.x;
    if (i >= NN * HH / 4) return;
    float alpha = alpha_p[0];
    float4 v = reinterpret_cast<float4*>(out)[i];
    v.x = v.x >= 0.f ? v.x : alpha * v.x;
    v.y = v.y >= 0.f ? v.y : alpha * v.y;
    v.z = v.z >= 0.f ? v.z : alpha * v.z;
    v.w = v.w >= 0.f ? v.w : alpha * v.w;
    reinterpret_cast<float4*>(out)[i] = v;
}

// ---------------------------------------------------------------------------
// kernel_launch
// Inputs (metadata order): X, rows, cols, vals, W, b, alpha
// ---------------------------------------------------------------------------
extern "C" void kernel_launch(void* const* d_in, const int* in_sizes, int n_in,
                              void* d_out, int out_size) {
    const float* X     = (const float*)d_in[0];
    const int*   rows  = (const int*)  d_in[1];
    const int*   cols  = (const int*)  d_in[2];
    const float* vals  = (const float*)d_in[3];
    const float* W     = (const float*)d_in[4];
    const float* b     = (const float*)d_in[5];
    const float* alpha = (const float*)d_in[6];
    float* out = (float*)d_out;

    // 1) repack weights
    repack_w_kernel<<<(K1 * DD * HH + 255) / 256, 256>>>(W);

    // 2) dense GEMM: Y = X @ W_all
    dim3 grid(NJ / BN, (NN + BM - 1) / BM);
    sgemm_kernel<<<grid, 256>>>(X);

    // 3) init out with bias sum
    bias_init_kernel<<<(NN * HH / 4 + 255) / 256, 256>>>(b, out);

    // 4) sparse scatter-accumulate (4 hops fused, one warp per edge)
    size_t total_threads = (size_t)K1 * EE * 32;
    spmm_kernel<<<(unsigned)((total_threads + 255) / 256), 256>>>(rows, cols, vals, out);

    // 5) PReLU
    prelu_kernel<<<(NN * HH / 4 + 255) / 256, 256>>>(out, alpha);
}

// round 3
// speedup vs baseline: 2.1531x; 2.1531x over previous
#include <cuda_runtime.h>
#include <cuda_bf16.h>
#include <cstdint>

// ---------------------------------------------------------------------------
// Problem constants
// ---------------------------------------------------------------------------
#define NN 50000
#define EE 400000
#define K1 4
#define DD 1280
#define HH 256
#define NJ 1024                 // K1 * HH
#define KA 2560                 // A' width: [Xh | Xl]
#define KB 3840                 // B' width: [Wh ; Wh ; Wl]
#define KTILES 60               // KB / 64
#define MTILES 391              // ceil(50000 / 128)
#define MPAD (MTILES * 128)     // 50048

// GEMM tiling
#define BM 128
#define BN 128
#define BK 64                   // bf16 elems per k-chunk (128 B rows)
#define STAGE_BYTES 32768       // A 16KB + B 16KB
#define NSTAGES 3
#define SMEM_TOTAL (NSTAGES * STAGE_BYTES)   // 96 KB

// ---------------------------------------------------------------------------
// Device scratch (zero-initialized; no allocations allowed)
// ---------------------------------------------------------------------------
__device__ __align__(16) __nv_bfloat16 g_A[(size_t)MPAD * KA];  // 256 MB
__device__ __align__(16) __nv_bfloat16 g_B[(size_t)NJ * KB];    // 7.9 MB
__device__ float g_Y[(size_t)NN * NJ];                          // 205 MB

// ---------------------------------------------------------------------------
// PTX helpers (family-generic ISA only: cp.async / ldmatrix / mma.sync)
// ---------------------------------------------------------------------------
__device__ __forceinline__ uint32_t smem_u32(const void* p) {
    uint32_t a;
    asm("{ .reg .u64 t; cvta.to.shared.u64 t, %1; cvt.u32.u64 %0, t; }" : "=r"(a) : "l"(p));
    return a;
}

__device__ __forceinline__ void cp16(uint32_t dst, const void* src) {
    asm volatile("cp.async.cg.shared.global [%0], [%1], 16;" :: "r"(dst), "l"(src));
}
#define CP_COMMIT() asm volatile("cp.async.commit_group;" ::: "memory")
#define CP_WAIT1()  asm volatile("cp.async.wait_group 1;" ::: "memory")

__device__ __forceinline__ void ldsm_x4(uint32_t* d, uint32_t addr) {
    asm volatile("ldmatrix.sync.aligned.m8n8.x4.shared.b16 {%0,%1,%2,%3}, [%4];"
                 : "=r"(d[0]), "=r"(d[1]), "=r"(d[2]), "=r"(d[3]) : "r"(addr));
}

__device__ __forceinline__ void mma16816(float* c, const uint32_t* a, const uint32_t* b) {
    asm volatile(
        "mma.sync.aligned.m16n8k16.row.col.f32.bf16.bf16.f32 "
        "{%0,%1,%2,%3}, {%4,%5,%6,%7}, {%8,%9}, {%0,%1,%2,%3};"
        : "+f"(c[0]), "+f"(c[1]), "+f"(c[2]), "+f"(c[3])
        : "r"(a[0]), "r"(a[1]), "r"(a[2]), "r"(a[3]), "r"(b[0]), "r"(b[1]));
}

// SW128 swizzle on 128-byte rows: byte_off ^ (((byte_off) >> 3) & 0x70)
// For row*128 + c*16 this reduces to XOR with ((row & 7) << 4).

// ---------------------------------------------------------------------------
// Pack A: X fp32 [N, D] -> g_A bf16 [MPAD, 2560] = [Xh | Xl]
// ---------------------------------------------------------------------------
__global__ void pack_a_kernel(const float* __restrict__ X) {
    int idx = blockIdx.x * blockDim.x + threadIdx.x;
    if (idx >= NN * (DD / 4)) return;
    int m = idx / (DD / 4);
    int q = idx % (DD / 4);
    float4 x = reinterpret_cast<const float4*>(X)[(size_t)m * (DD / 4) + q];

    __nv_bfloat16 h0 = __float2bfloat16_rn(x.x);
    __nv_bfloat16 h1 = __float2bfloat16_rn(x.y);
    __nv_bfloat16 h2 = __float2bfloat16_rn(x.z);
    __nv_bfloat16 h3 = __float2bfloat16_rn(x.w);
    __nv_bfloat16 l0 = __float2bfloat16_rn(x.x - __bfloat162float(h0));
    __nv_bfloat16 l1 = __float2bfloat16_rn(x.y - __bfloat162float(h1));
    __nv_bfloat16 l2 = __float2bfloat16_rn(x.z - __bfloat162float(h2));
    __nv_bfloat16 l3 = __float2bfloat16_rn(x.w - __bfloat162float(h3));

    __nv_bfloat162 ha = __nv_bfloat162(h0, h1), hb = __nv_bfloat162(h2, h3);
    __nv_bfloat162 la = __nv_bfloat162(l0, l1), lb = __nv_bfloat162(l2, l3);
    uint2 hv, lv;
    hv.x = *reinterpret_cast<uint32_t*>(&ha); hv.y = *reinterpret_cast<uint32_t*>(&hb);
    lv.x = *reinterpret_cast<uint32_t*>(&la); lv.y = *reinterpret_cast<uint32_t*>(&lb);

    __nv_bfloat16* row = g_A + (size_t)m * KA;
    *reinterpret_cast<uint2*>(row + q * 4) = hv;
    *reinterpret_cast<uint2*>(row + DD + q * 4) = lv;
}

// ---------------------------------------------------------------------------
// Pack B: W fp32 [K1, D, H] -> g_B bf16 [n = k1*H+h][3840] = [Wh | Wh | Wl]
// ---------------------------------------------------------------------------
__global__ void pack_b_kernel(const float* __restrict__ W) {
    int idx = blockIdx.x * blockDim.x + threadIdx.x;
    if (idx >= K1 * DD * HH) return;
    int h = idx % HH;
    int d = (idx / HH) % DD;
    int k1 = idx / (HH * DD);
    float w = W[idx];
    __nv_bfloat16 hi = __float2bfloat16_rn(w);
    __nv_bfloat16 lo = __float2bfloat16_rn(w - __bfloat162float(hi));
    int n = k1 * HH + h;
    __nv_bfloat16* row = g_B + (size_t)n * KB;
    row[d] = hi;
    row[DD + d] = hi;
    row[2 * DD + d] = lo;
}

// ---------------------------------------------------------------------------
// GEMM: g_Y[m, n] = sum over 3 segments:
//   seg0: Xh (A k-off 0)    x Wh (B rows [0,1280))
//   seg1: Xl (A k-off 1280) x Wh (B rows [1280,2560))
//   seg2: Xh (A k-off 0)    x Wl (B rows [2560,3840))
// mma.sync m16n8k16 bf16, 8 warps (2x4), warp tile 64x32, 3-stage cp.async.
// ---------------------------------------------------------------------------
__device__ __forceinline__ void issue_stage(int kc, uint32_t sbase, int mt, int nt, int tid) {
    if (kc < KTILES) {
        int seg = kc / 20, kk = kc % 20;
        int akb = (seg == 1 ? DD : 0) + kk * BK;   // A k-offset (elems)
        int bkb = kc * BK;                          // B k-offset (elems)
        uint32_t sA = sbase + (uint32_t)(kc % NSTAGES) * STAGE_BYTES;
        uint32_t sB = sA + 16384;
        const __nv_bfloat16* Ab = g_A + (size_t)(mt * BM) * KA + akb;
        const __nv_bfloat16* Bb = g_B + (size_t)(nt * BN) * KB + bkb;
        #pragma unroll
        for (int i = 0; i < 4; i++) {
            int idx = tid + i * 256;
            int row = idx >> 3;
            int c = idx & 7;
            uint32_t sw = (uint32_t)((c * 16) ^ ((row & 7) << 4));
            cp16(sA + row * 128 + sw, Ab + (size_t)row * KA + c * 8);
            cp16(sB + row * 128 + sw, Bb + (size_t)row * KB + c * 8);
        }
    }
    CP_COMMIT();
}

__global__ __launch_bounds__(256, 1) void gemm_kernel() {
    extern __shared__ char smem[];
    uint32_t sbase = smem_u32(smem);
    int tid = threadIdx.x, lane = tid & 31, wid = tid >> 5;
    int nt = blockIdx.x, mt = blockIdx.y;
    int wm = wid >> 2, wn = wid & 3;    // warp grid 2 (M) x 4 (N)

    float acc[4][4][4];
    #pragma unroll
    for (int i = 0; i < 4; i++)
        #pragma unroll
        for (int j = 0; j < 4; j++)
            #pragma unroll
            for (int r = 0; r < 4; r++) acc[i][j][r] = 0.0f;

    issue_stage(0, sbase, mt, nt, tid);
    issue_stage(1, sbase, mt, nt, tid);

    // precompute ldmatrix lane coords
    int a_r = lane & 15, a_g = lane >> 4;          // A: row-in-tile16, k-chunk sel
    int b_g = lane >> 3, b_r = lane & 7;           // B: group, row
    int b_nrow_base = wn * 32 + (b_g >> 1) * 8 + b_r;
    int b_csel = b_g & 1;

    for (int kc = 0; kc < KTILES; kc++) {
        CP_WAIT1();
        __syncthreads();
        issue_stage(kc + 2, sbase, mt, nt, tid);

        uint32_t sA = sbase + (uint32_t)(kc % NSTAGES) * STAGE_BYTES;
        uint32_t sB = sA + 16384;

        #pragma unroll
        for (int ks = 0; ks < 4; ks++) {
            uint32_t af[4][4], bf[2][4];
            #pragma unroll
            for (int mi = 0; mi < 4; mi++) {
                int row = wm * 64 + mi * 16 + a_r;
                int col16 = ks * 2 + a_g;
                uint32_t addr = sA + row * 128 + (uint32_t)((col16 * 16) ^ ((row & 7) << 4));
                ldsm_x4(af[mi], addr);
            }
            #pragma unroll
            for (int p = 0; p < 2; p++) {
                int nrow = b_nrow_base + p * 16;
                int col16 = ks * 2 + b_csel;
                uint32_t addr = sB + nrow * 128 + (uint32_t)((col16 * 16) ^ ((nrow & 7) << 4));
                ldsm_x4(bf[p], addr);
            }
            #pragma unroll
            for (int mi = 0; mi < 4; mi++)
                #pragma unroll
                for (int ni = 0; ni < 4; ni++)
                    mma16816(acc[mi][ni], af[mi], &bf[ni >> 1][(ni & 1) * 2]);
        }
    }

    // epilogue: direct fp32 stores into g_Y
    int nbase = nt * BN + wn * 32;
    #pragma unroll
    for (int mi = 0; mi < 4; mi++) {
        int row0 = mt * BM + wm * 64 + mi * 16 + (lane >> 2);
        #pragma unroll
        for (int ni = 0; ni < 4; ni++) {
            int col = nbase + ni * 8 + (lane & 3) * 2;
            if (row0 < NN)
                *reinterpret_cast<float2*>(g_Y + (size_t)row0 * NJ + col) =
                    make_float2(acc[mi][ni][0], acc[mi][ni][1]);
            if (row0 + 8 < NN)
                *reinterpret_cast<float2*>(g_Y + (size_t)(row0 + 8) * NJ + col) =
                    make_float2(acc[mi][ni][2], acc[mi][ni][3]);
        }
    }
}

// ---------------------------------------------------------------------------
// Init out[n,h] = sum_k b[k,h]
// ---------------------------------------------------------------------------
__global__ void bias_init_kernel(const float* __restrict__ b, float* __restrict__ out) {
    int i = blockIdx.x * blockDim.x + threadIdx.x;
    if (i >= NN * HH / 4) return;
    int h4 = i & 63;
    const float4* b4 = reinterpret_cast<const float4*>(b);
    float4 s0 = b4[0 * 64 + h4], s1 = b4[1 * 64 + h4], s2 = b4[2 * 64 + h4], s3 = b4[3 * 64 + h4];
    reinterpret_cast<float4*>(out)[i] =
        make_float4(s0.x + s1.x + s2.x + s3.x, s0.y + s1.y + s2.y + s3.y,
                    s0.z + s1.z + s2.z + s3.z, s0.w + s1.w + s2.w + s3.w);
}

// ---------------------------------------------------------------------------
// SpMM scatter: out[rows[k,e], :] += vals[k,e] * Y[cols[k,e], k*H:(k+1)*H]
// ---------------------------------------------------------------------------
__global__ void spmm_kernel(const int* __restrict__ rows, const int* __restrict__ cols,
                            const float* __restrict__ vals, float* __restrict__ out) {
    int gw = (int)((blockIdx.x * (size_t)blockDim.x + threadIdx.x) >> 5);
    int lane = threadIdx.x & 31;
    if (gw >= K1 * EE) return;
    int k = gw / EE;
    int r = rows[gw];
    int c = cols[gw];
    float v = vals[gw];
    const float4* yp = reinterpret_cast<const float4*>(g_Y + (size_t)c * NJ + k * HH);
    float* op = out + (size_t)r * HH;
    float4 y0 = yp[lane];
    float4 y1 = yp[lane + 32];
    float* a0 = op + lane * 4;
    float* a1 = op + (lane + 32) * 4;
    asm volatile("red.global.add.v4.f32 [%0], {%1,%2,%3,%4};"
                 :: "l"(a0), "f"(v * y0.x), "f"(v * y0.y), "f"(v * y0.z), "f"(v * y0.w) : "memory");
    asm volatile("red.global.add.v4.f32 [%0], {%1,%2,%3,%4};"
                 :: "l"(a1), "f"(v * y1.x), "f"(v * y1.y), "f"(v * y1.z), "f"(v * y1.w) : "memory");
}

// ---------------------------------------------------------------------------
// PReLU epilogue
// ---------------------------------------------------------------------------
__global__ void prelu_kernel(float* __restrict__ out, const float* __restrict__ alpha_p) {
    int i = blockIdx.x * blockDim.x + threadIdx.x;
    if (i >= NN * HH / 4) return;
    float alpha = alpha_p[0];
    float4 v = reinterpret_cast<float4*>(out)[i];
    v.x = v.x >= 0.f ? v.x : alpha * v.x;
    v.y = v.y >= 0.f ? v.y : alpha * v.y;
    v.z = v.z >= 0.f ? v.z : alpha * v.z;
    v.w = v.w >= 0.f ? v.w : alpha * v.w;
    reinterpret_cast<float4*>(out)[i] = v;
}

// ---------------------------------------------------------------------------
// kernel_launch — inputs: X, rows, cols, vals, W, b, alpha
// ---------------------------------------------------------------------------
extern "C" void kernel_launch(void* const* d_in, const int* in_sizes, int n_in,
                              void* d_out, int out_size) {
    const float* X     = (const float*)d_in[0];
    const int*   rows  = (const int*)  d_in[1];
    const int*   cols  = (const int*)  d_in[2];
    const float* vals  = (const float*)d_in[3];
    const float* W     = (const float*)d_in[4];
    const float* b     = (const float*)d_in[5];
    const float* alpha = (const float*)d_in[6];
    float* out = (float*)d_out;

    cudaFuncSetAttribute(gemm_kernel, cudaFuncAttributeMaxDynamicSharedMemorySize, SMEM_TOTAL);

    pack_a_kernel<<<(NN * (DD / 4) + 255) / 256, 256>>>(X);
    pack_b_kernel<<<(K1 * DD * HH + 255) / 256, 256>>>(W);

    gemm_kernel<<<dim3(NJ / BN, MTILES), 256, SMEM_TOTAL>>>();

    bias_init_kernel<<<(NN * HH / 4 + 255) / 256, 256>>>(b, out);

    size_t total_threads = (size_t)K1 * EE * 32;
    spmm_kernel<<<(unsigned)((total_threads + 255) / 256), 256>>>(rows, cols, vals, out);

    prelu_kernel<<<(NN * HH / 4 + 255) / 256, 256>>>(out, alpha);
}

// round 4
// speedup vs baseline: 2.8899x; 1.3422x over previous
#include <cuda_runtime.h>
#include <cuda_fp16.h>
#include <cstdint>

// ---------------------------------------------------------------------------
// Problem constants
// ---------------------------------------------------------------------------
#define NN 50000
#define EE 400000
#define K1 4
#define DD 1280
#define HH 256
#define NJ 1024                 // K1 * HH
#define KK 2560                 // split K: [Xh | Xl] x [Wh ; Wh]
#define KTILES 40               // KK / 64
#define MTILES 391              // ceil(50000 / 128)
#define MPAD (MTILES * 128)     // 50048

// GEMM tiling
#define BM 128
#define BN 128
#define BK 64                   // fp16 elems per k-chunk (128 B rows)
#define STAGE_BYTES 32768       // A 16KB + B 16KB
#define NSTAGES 3
#define SMEM_TOTAL (NSTAGES * STAGE_BYTES)   // 96 KB

// ---------------------------------------------------------------------------
// Device scratch (no allocations allowed)
// ---------------------------------------------------------------------------
__device__ __align__(16) __half g_A[(size_t)MPAD * KK];   // 256 MB
__device__ __align__(16) __half g_B[(size_t)NJ * KK];     // 5.2 MB
__device__ float g_Y[(size_t)NN * NJ];                    // 205 MB

// ---------------------------------------------------------------------------
// PTX helpers (family-generic ISA: cp.async / ldmatrix / mma.sync)
// ---------------------------------------------------------------------------
__device__ __forceinline__ uint32_t smem_u32(const void* p) {
    uint32_t a;
    asm("{ .reg .u64 t; cvta.to.shared.u64 t, %1; cvt.u32.u64 %0, t; }" : "=r"(a) : "l"(p));
    return a;
}

__device__ __forceinline__ void cp16(uint32_t dst, const void* src) {
    asm volatile("cp.async.cg.shared.global [%0], [%1], 16;" :: "r"(dst), "l"(src));
}
#define CP_COMMIT() asm volatile("cp.async.commit_group;" ::: "memory")
#define CP_WAIT1()  asm volatile("cp.async.wait_group 1;" ::: "memory")

__device__ __forceinline__ void ldsm_x4(uint32_t* d, uint32_t addr) {
    asm volatile("ldmatrix.sync.aligned.m8n8.x4.shared.b16 {%0,%1,%2,%3}, [%4];"
                 : "=r"(d[0]), "=r"(d[1]), "=r"(d[2]), "=r"(d[3]) : "r"(addr));
}

__device__ __forceinline__ void mma16816(float* c, const uint32_t* a, const uint32_t* b) {
    asm volatile(
        "mma.sync.aligned.m16n8k16.row.col.f32.f16.f16.f32 "
        "{%0,%1,%2,%3}, {%4,%5,%6,%7}, {%8,%9}, {%0,%1,%2,%3};"
        : "+f"(c[0]), "+f"(c[1]), "+f"(c[2]), "+f"(c[3])
        : "r"(a[0]), "r"(a[1]), "r"(a[2]), "r"(a[3]), "r"(b[0]), "r"(b[1]));
}

// SW128 swizzle: for addr = row*128 + c*16, swizzled c16 = c16 ^ (row & 7).

// ---------------------------------------------------------------------------
// Pack A: X fp32 [N, D] -> g_A fp16 [MPAD, 2560] = [Xh | Xl]
// ---------------------------------------------------------------------------
__global__ void pack_a_kernel(const float* __restrict__ X) {
    int idx = blockIdx.x * blockDim.x + threadIdx.x;
    if (idx >= NN * (DD / 4)) return;
    int m = idx / (DD / 4);
    int q = idx % (DD / 4);
    float4 x = reinterpret_cast<const float4*>(X)[(size_t)m * (DD / 4) + q];

    __half h0 = __float2half_rn(x.x);
    __half h1 = __float2half_rn(x.y);
    __half h2 = __float2half_rn(x.z);
    __half h3 = __float2half_rn(x.w);
    __half l0 = __float2half_rn(x.x - __half2float(h0));
    __half l1 = __float2half_rn(x.y - __half2float(h1));
    __half l2 = __float2half_rn(x.z - __half2float(h2));
    __half l3 = __float2half_rn(x.w - __half2float(h3));

    __half2 ha = __halves2half2(h0, h1), hb = __halves2half2(h2, h3);
    __half2 la = __halves2half2(l0, l1), lb = __halves2half2(l2, l3);
    uint2 hv, lv;
    hv.x = *reinterpret_cast<uint32_t*>(&ha); hv.y = *reinterpret_cast<uint32_t*>(&hb);
    lv.x = *reinterpret_cast<uint32_t*>(&la); lv.y = *reinterpret_cast<uint32_t*>(&lb);

    __half* row = g_A + (size_t)m * KK;
    *reinterpret_cast<uint2*>(row + q * 4) = hv;
    *reinterpret_cast<uint2*>(row + DD + q * 4) = lv;
}

// ---------------------------------------------------------------------------
// Pack B: W fp32 [K1, D, H] -> g_B fp16 [n = k1*H+h][2560] = [Wh | Wh]
// ---------------------------------------------------------------------------
__global__ void pack_b_kernel(const float* __restrict__ W) {
    int idx = blockIdx.x * blockDim.x + threadIdx.x;
    if (idx >= K1 * DD * HH) return;
    int h = idx % HH;
    int d = (idx / HH) % DD;
    int k1 = idx / (HH * DD);
    __half hi = __float2half_rn(W[idx]);
    int n = k1 * HH + h;
    __half* row = g_B + (size_t)n * KK;
    row[d] = hi;
    row[DD + d] = hi;
}

// ---------------------------------------------------------------------------
// GEMM: g_Y = A'[MPAD x 2560] @ B'[1024 x 2560]^T  (fp16 in, fp32 accum)
// mma.sync m16n8k16, 8 warps (2x4), warp tile 64x32, 3-stage cp.async.
// ---------------------------------------------------------------------------
__device__ __forceinline__ void issue_stage(int kc, uint32_t sbase, int mt, int nt, int tid) {
    if (kc < KTILES) {
        int kb = kc * BK;
        uint32_t sA = sbase + (uint32_t)(kc % NSTAGES) * STAGE_BYTES;
        uint32_t sB = sA + 16384;
        const __half* Ab = g_A + (size_t)(mt * BM) * KK + kb;
        const __half* Bb = g_B + (size_t)(nt * BN) * KK + kb;
        #pragma unroll
        for (int i = 0; i < 4; i++) {
            int idx = tid + i * 256;
            int row = idx >> 3;
            int c = idx & 7;
            uint32_t sw = (uint32_t)((c * 16) ^ ((row & 7) << 4));
            cp16(sA + row * 128 + sw, Ab + (size_t)row * KK + c * 8);
            cp16(sB + row * 128 + sw, Bb + (size_t)row * KK + c * 8);
        }
    }
    CP_COMMIT();
}

__global__ __launch_bounds__(256, 1) void gemm_kernel() {
    extern __shared__ char smem[];
    uint32_t sbase = smem_u32(smem);
    int tid = threadIdx.x, lane = tid & 31, wid = tid >> 5;
    int nt = blockIdx.x, mt = blockIdx.y;
    int wm = wid >> 2, wn = wid & 3;    // warp grid 2 (M) x 4 (N)

    float acc[4][4][4];
    #pragma unroll
    for (int i = 0; i < 4; i++)
        #pragma unroll
        for (int j = 0; j < 4; j++)
            #pragma unroll
            for (int r = 0; r < 4; r++) acc[i][j][r] = 0.0f;

    issue_stage(0, sbase, mt, nt, tid);
    issue_stage(1, sbase, mt, nt, tid);

    int a_r = lane & 15, a_g = lane >> 4;          // A ldmatrix coords
    int b_g = lane >> 3, b_r = lane & 7;           // B ldmatrix coords
    int b_nrow_base = wn * 32 + (b_g >> 1) * 8 + b_r;
    int b_csel = b_g & 1;

    for (int kc = 0; kc < KTILES; kc++) {
        CP_WAIT1();
        __syncthreads();
        issue_stage(kc + 2, sbase, mt, nt, tid);

        uint32_t sA = sbase + (uint32_t)(kc % NSTAGES) * STAGE_BYTES;
        uint32_t sB = sA + 16384;

        #pragma unroll
        for (int ks = 0; ks < 4; ks++) {
            uint32_t af[4][4], bf[2][4];
            #pragma unroll
            for (int mi = 0; mi < 4; mi++) {
                int row = wm * 64 + mi * 16 + a_r;
                int col16 = ks * 2 + a_g;
                uint32_t addr = sA + row * 128 + (uint32_t)((col16 * 16) ^ ((row & 7) << 4));
                ldsm_x4(af[mi], addr);
            }
            #pragma unroll
            for (int p = 0; p < 2; p++) {
                int nrow = b_nrow_base + p * 16;
                int col16 = ks * 2 + b_csel;
                uint32_t addr = sB + nrow * 128 + (uint32_t)((col16 * 16) ^ ((nrow & 7) << 4));
                ldsm_x4(bf[p], addr);
            }
            #pragma unroll
            for (int mi = 0; mi < 4; mi++)
                #pragma unroll
                for (int ni = 0; ni < 4; ni++)
                    mma16816(acc[mi][ni], af[mi], &bf[ni >> 1][(ni & 1) * 2]);
        }
    }

    // epilogue: direct fp32 stores into g_Y
    int nbase = nt * BN + wn * 32;
    #pragma unroll
    for (int mi = 0; mi < 4; mi++) {
        int row0 = mt * BM + wm * 64 + mi * 16 + (lane >> 2);
        #pragma unroll
        for (int ni = 0; ni < 4; ni++) {
            int col = nbase + ni * 8 + (lane & 3) * 2;
            if (row0 < NN)
                *reinterpret_cast<float2*>(g_Y + (size_t)row0 * NJ + col) =
                    make_float2(acc[mi][ni][0], acc[mi][ni][1]);
            if (row0 + 8 < NN)
                *reinterpret_cast<float2*>(g_Y + (size_t)(row0 + 8) * NJ + col) =
                    make_float2(acc[mi][ni][2], acc[mi][ni][3]);
        }
    }
}

// ---------------------------------------------------------------------------
// Init out[n,h] = sum_k b[k,h]
// ---------------------------------------------------------------------------
__global__ void bias_init_kernel(const float* __restrict__ b, float* __restrict__ out) {
    int i = blockIdx.x * blockDim.x + threadIdx.x;
    if (i >= NN * HH / 4) return;
    int h4 = i & 63;
    const float4* b4 = reinterpret_cast<const float4*>(b);
    float4 s0 = b4[0 * 64 + h4], s1 = b4[1 * 64 + h4], s2 = b4[2 * 64 + h4], s3 = b4[3 * 64 + h4];
    reinterpret_cast<float4*>(out)[i] =
        make_float4(s0.x + s1.x + s2.x + s3.x, s0.y + s1.y + s2.y + s3.y,
                    s0.z + s1.z + s2.z + s3.z, s0.w + s1.w + s2.w + s3.w);
}

// ---------------------------------------------------------------------------
// SpMM scatter: out[rows[k,e], :] += vals[k,e] * Y[cols[k,e], k*H:(k+1)*H]
// ---------------------------------------------------------------------------
__global__ void spmm_kernel(const int* __restrict__ rows, const int* __restrict__ cols,
                            const float* __restrict__ vals, float* __restrict__ out) {
    int gw = (int)((blockIdx.x * (size_t)blockDim.x + threadIdx.x) >> 5);
    int lane = threadIdx.x & 31;
    if (gw >= K1 * EE) return;
    int k = gw / EE;
    int r = rows[gw];
    int c = cols[gw];
    float v = vals[gw];
    const float4* yp = reinterpret_cast<const float4*>(g_Y + (size_t)c * NJ + k * HH);
    float* op = out + (size_t)r * HH;
    float4 y0 = yp[lane];
    float4 y1 = yp[lane + 32];
    float* a0 = op + lane * 4;
    float* a1 = op + (lane + 32) * 4;
    asm volatile("red.global.add.v4.f32 [%0], {%1,%2,%3,%4};"
                 :: "l"(a0), "f"(v * y0.x), "f"(v * y0.y), "f"(v * y0.z), "f"(v * y0.w) : "memory");
    asm volatile("red.global.add.v4.f32 [%0], {%1,%2,%3,%4};"
                 :: "l"(a1), "f"(v * y1.x), "f"(v * y1.y), "f"(v * y1.z), "f"(v * y1.w) : "memory");
}

// ---------------------------------------------------------------------------
// PReLU epilogue
// ---------------------------------------------------------------------------
__global__ void prelu_kernel(float* __restrict__ out, const float* __restrict__ alpha_p) {
    int i = blockIdx.x * blockDim.x + threadIdx.x;
    if (i >= NN * HH / 4) return;
    float alpha = alpha_p[0];
    float4 v = reinterpret_cast<float4*>(out)[i];
    v.x = v.x >= 0.f ? v.x : alpha * v.x;
    v.y = v.y >= 0.f ? v.y : alpha * v.y;
    v.z = v.z >= 0.f ? v.z : alpha * v.z;
    v.w = v.w >= 0.f ? v.w : alpha * v.w;
    reinterpret_cast<float4*>(out)[i] = v;
}

// ---------------------------------------------------------------------------
// kernel_launch — inputs: X, rows, cols, vals, W, b, alpha
// ---------------------------------------------------------------------------
extern "C" void kernel_launch(void* const* d_in, const int* in_sizes, int n_in,
                              void* d_out, int out_size) {
    const float* X     = (const float*)d_in[0];
    const int*   rows  = (const int*)  d_in[1];
    const int*   cols  = (const int*)  d_in[2];
    const float* vals  = (const float*)d_in[3];
    const float* W     = (const float*)d_in[4];
    const float* b     = (const float*)d_in[5];
    const float* alpha = (const float*)d_in[6];
    float* out = (float*)d_out;

    cudaFuncSetAttribute(gemm_kernel, cudaFuncAttributeMaxDynamicSharedMemorySize, SMEM_TOTAL);

    pack_a_kernel<<<(NN * (DD / 4) + 255) / 256, 256>>>(X);
    pack_b_kernel<<<(K1 * DD * HH + 255) / 256, 256>>>(W);

    gemm_kernel<<<dim3(NJ / BN, MTILES), 256, SMEM_TOTAL>>>();

    bias_init_kernel<<<(NN * HH / 4 + 255) / 256, 256>>>(b, out);

    size_t total_threads = (size_t)K1 * EE * 32;
    spmm_kernel<<<(unsigned)((total_threads + 255) / 256), 256>>>(rows, cols, vals, out);

    prelu_kernel<<<(NN * HH / 4 + 255) / 256, 256>>>(out, alpha);
}

// round 5
// speedup vs baseline: 4.2217x; 1.4608x over previous
#include <cuda_runtime.h>
#include <cuda_fp16.h>
#include <cstdint>

// ---------------------------------------------------------------------------
// Problem constants
// ---------------------------------------------------------------------------
#define NN 50000
#define EE 400000
#define K1 4
#define DD 1280
#define HH 256
#define NJ 1024                 // K1 * HH
#define KK 1280                 // plain fp16 GEMM K
#define KTILES 20               // KK / 64
#define MTILES 391              // ceil(50000 / 128)
#define MPAD (MTILES * 128)     // 50048

// GEMM tiling
#define BM 128
#define BN 128
#define BK 64                   // fp16 elems per k-chunk (128 B rows)
#define STAGE_BYTES 32768       // A 16KB + B 16KB
#define NSTAGES 3
#define SMEM_TOTAL (NSTAGES * STAGE_BYTES)   // 96 KB

// ---------------------------------------------------------------------------
// Device scratch (no allocations allowed)
// ---------------------------------------------------------------------------
__device__ __align__(16) __half g_A[(size_t)MPAD * KK];   // 128 MB
__device__ __align__(16) __half g_B[(size_t)NJ * KK];     // 2.6 MB
__device__ float g_Y[(size_t)NN * NJ];                    // 205 MB

// ---------------------------------------------------------------------------
// PTX helpers (family-generic ISA: cp.async / ldmatrix / mma.sync)
// ---------------------------------------------------------------------------
__device__ __forceinline__ uint32_t smem_u32(const void* p) {
    uint32_t a;
    asm("{ .reg .u64 t; cvta.to.shared.u64 t, %1; cvt.u32.u64 %0, t; }" : "=r"(a) : "l"(p));
    return a;
}

__device__ __forceinline__ void cp16(uint32_t dst, const void* src) {
    asm volatile("cp.async.cg.shared.global [%0], [%1], 16;" :: "r"(dst), "l"(src));
}
#define CP_COMMIT() asm volatile("cp.async.commit_group;" ::: "memory")
#define CP_WAIT1()  asm volatile("cp.async.wait_group 1;" ::: "memory")

__device__ __forceinline__ void ldsm_x4(uint32_t* d, uint32_t addr) {
    asm volatile("ldmatrix.sync.aligned.m8n8.x4.shared.b16 {%0,%1,%2,%3}, [%4];"
                 : "=r"(d[0]), "=r"(d[1]), "=r"(d[2]), "=r"(d[3]) : "r"(addr));
}

__device__ __forceinline__ void mma16816(float* c, const uint32_t* a, const uint32_t* b) {
    asm volatile(
        "mma.sync.aligned.m16n8k16.row.col.f32.f16.f16.f32 "
        "{%0,%1,%2,%3}, {%4,%5,%6,%7}, {%8,%9}, {%0,%1,%2,%3};"
        : "+f"(c[0]), "+f"(c[1]), "+f"(c[2]), "+f"(c[3])
        : "r"(a[0]), "r"(a[1]), "r"(a[2]), "r"(a[3]), "r"(b[0]), "r"(b[1]));
}

// SW128 swizzle: for addr = row*128 + c*16, swizzled c16 = c16 ^ (row & 7).

// ---------------------------------------------------------------------------
// Pack A: X fp32 [N, D] -> g_A fp16 [MPAD, 1280]
// ---------------------------------------------------------------------------
__global__ void pack_a_kernel(const float* __restrict__ X) {
    int idx = blockIdx.x * blockDim.x + threadIdx.x;
    if (idx >= NN * (DD / 4)) return;
    int m = idx / (DD / 4);
    int q = idx % (DD / 4);
    float4 x = reinterpret_cast<const float4*>(X)[(size_t)m * (DD / 4) + q];

    __half2 ha = __halves2half2(__float2half_rn(x.x), __float2half_rn(x.y));
    __half2 hb = __halves2half2(__float2half_rn(x.z), __float2half_rn(x.w));
    uint2 hv;
    hv.x = *reinterpret_cast<uint32_t*>(&ha);
    hv.y = *reinterpret_cast<uint32_t*>(&hb);
    *reinterpret_cast<uint2*>(g_A + (size_t)m * KK + q * 4) = hv;
}

// ---------------------------------------------------------------------------
// Pack B: W fp32 [K1, D, H] -> g_B fp16 [n = k1*H+h][1280]
// ---------------------------------------------------------------------------
__global__ void pack_b_kernel(const float* __restrict__ W) {
    int idx = blockIdx.x * blockDim.x + threadIdx.x;
    if (idx >= K1 * DD * HH) return;
    int h = idx % HH;
    int d = (idx / HH) % DD;
    int k1 = idx / (HH * DD);
    int n = k1 * HH + h;
    g_B[(size_t)n * KK + d] = __float2half_rn(W[idx]);
}

// ---------------------------------------------------------------------------
// GEMM: g_Y = A[MPAD x 1280] @ B[1024 x 1280]^T  (fp16 in, fp32 accum)
// mma.sync m16n8k16, 8 warps (2x4), warp tile 64x32, 3-stage cp.async.
// ---------------------------------------------------------------------------
__device__ __forceinline__ void issue_stage(int kc, uint32_t sbase, int mt, int nt, int tid) {
    if (kc < KTILES) {
        int kb = kc * BK;
        uint32_t sA = sbase + (uint32_t)(kc % NSTAGES) * STAGE_BYTES;
        uint32_t sB = sA + 16384;
        const __half* Ab = g_A + (size_t)(mt * BM) * KK + kb;
        const __half* Bb = g_B + (size_t)(nt * BN) * KK + kb;
        #pragma unroll
        for (int i = 0; i < 4; i++) {
            int idx = tid + i * 256;
            int row = idx >> 3;
            int c = idx & 7;
            uint32_t sw = (uint32_t)((c * 16) ^ ((row & 7) << 4));
            cp16(sA + row * 128 + sw, Ab + (size_t)row * KK + c * 8);
            cp16(sB + row * 128 + sw, Bb + (size_t)row * KK + c * 8);
        }
    }
    CP_COMMIT();
}

__global__ __launch_bounds__(256, 1) void gemm_kernel() {
    extern __shared__ char smem[];
    uint32_t sbase = smem_u32(smem);
    int tid = threadIdx.x, lane = tid & 31, wid = tid >> 5;
    int nt = blockIdx.x, mt = blockIdx.y;
    int wm = wid >> 2, wn = wid & 3;    // warp grid 2 (M) x 4 (N)

    float acc[4][4][4];
    #pragma unroll
    for (int i = 0; i < 4; i++)
        #pragma unroll
        for (int j = 0; j < 4; j++)
            #pragma unroll
            for (int r = 0; r < 4; r++) acc[i][j][r] = 0.0f;

    issue_stage(0, sbase, mt, nt, tid);
    issue_stage(1, sbase, mt, nt, tid);

    int a_r = lane & 15, a_g = lane >> 4;          // A ldmatrix coords
    int b_g = lane >> 3, b_r = lane & 7;           // B ldmatrix coords
    int b_nrow_base = wn * 32 + (b_g >> 1) * 8 + b_r;
    int b_csel = b_g & 1;

    for (int kc = 0; kc < KTILES; kc++) {
        CP_WAIT1();
        __syncthreads();
        issue_stage(kc + 2, sbase, mt, nt, tid);

        uint32_t sA = sbase + (uint32_t)(kc % NSTAGES) * STAGE_BYTES;
        uint32_t sB = sA + 16384;

        #pragma unroll
        for (int ks = 0; ks < 4; ks++) {
            uint32_t af[4][4], bf[2][4];
            #pragma unroll
            for (int mi = 0; mi < 4; mi++) {
                int row = wm * 64 + mi * 16 + a_r;
                int col16 = ks * 2 + a_g;
                uint32_t addr = sA + row * 128 + (uint32_t)((col16 * 16) ^ ((row & 7) << 4));
                ldsm_x4(af[mi], addr);
            }
            #pragma unroll
            for (int p = 0; p < 2; p++) {
                int nrow = b_nrow_base + p * 16;
                int col16 = ks * 2 + b_csel;
                uint32_t addr = sB + nrow * 128 + (uint32_t)((col16 * 16) ^ ((nrow & 7) << 4));
                ldsm_x4(bf[p], addr);
            }
            #pragma unroll
            for (int mi = 0; mi < 4; mi++)
                #pragma unroll
                for (int ni = 0; ni < 4; ni++)
                    mma16816(acc[mi][ni], af[mi], &bf[ni >> 1][(ni & 1) * 2]);
        }
    }

    // epilogue: direct fp32 stores into g_Y
    int nbase = nt * BN + wn * 32;
    #pragma unroll
    for (int mi = 0; mi < 4; mi++) {
        int row0 = mt * BM + wm * 64 + mi * 16 + (lane >> 2);
        #pragma unroll
        for (int ni = 0; ni < 4; ni++) {
            int col = nbase + ni * 8 + (lane & 3) * 2;
            if (row0 < NN)
                *reinterpret_cast<float2*>(g_Y + (size_t)row0 * NJ + col) =
                    make_float2(acc[mi][ni][0], acc[mi][ni][1]);
            if (row0 + 8 < NN)
                *reinterpret_cast<float2*>(g_Y + (size_t)(row0 + 8) * NJ + col) =
                    make_float2(acc[mi][ni][2], acc[mi][ni][3]);
        }
    }
}

// ---------------------------------------------------------------------------
// Init out[n,h] = sum_k b[k,h]
// ---------------------------------------------------------------------------
__global__ void bias_init_kernel(const float* __restrict__ b, float* __restrict__ out) {
    int i = blockIdx.x * blockDim.x + threadIdx.x;
    if (i >= NN * HH / 4) return;
    int h4 = i & 63;
    const float4* b4 = reinterpret_cast<const float4*>(b);
    float4 s0 = b4[0 * 64 + h4], s1 = b4[1 * 64 + h4], s2 = b4[2 * 64 + h4], s3 = b4[3 * 64 + h4];
    reinterpret_cast<float4*>(out)[i] =
        make_float4(s0.x + s1.x + s2.x + s3.x, s0.y + s1.y + s2.y + s3.y,
                    s0.z + s1.z + s2.z + s3.z, s0.w + s1.w + s2.w + s3.w);
}

// ---------------------------------------------------------------------------
// SpMM scatter: out[rows[k,e], :] += vals[k,e] * Y[cols[k,e], k*H:(k+1)*H]
// ---------------------------------------------------------------------------
__global__ void spmm_kernel(const int* __restrict__ rows, const int* __restrict__ cols,
                            const float* __restrict__ vals, float* __restrict__ out) {
    int gw = (int)((blockIdx.x * (size_t)blockDim.x + threadIdx.x) >> 5);
    int lane = threadIdx.x & 31;
    if (gw >= K1 * EE) return;
    int k = gw / EE;
    int r = rows[gw];
    int c = cols[gw];
    float v = vals[gw];
    const float4* yp = reinterpret_cast<const float4*>(g_Y + (size_t)c * NJ + k * HH);
    float* op = out + (size_t)r * HH;
    float4 y0 = yp[lane];
    float4 y1 = yp[lane + 32];
    float* a0 = op + lane * 4;
    float* a1 = op + (lane + 32) * 4;
    asm volatile("red.global.add.v4.f32 [%0], {%1,%2,%3,%4};"
                 :: "l"(a0), "f"(v * y0.x), "f"(v * y0.y), "f"(v * y0.z), "f"(v * y0.w) : "memory");
    asm volatile("red.global.add.v4.f32 [%0], {%1,%2,%3,%4};"
                 :: "l"(a1), "f"(v * y1.x), "f"(v * y1.y), "f"(v * y1.z), "f"(v * y1.w) : "memory");
}

// ---------------------------------------------------------------------------
// PReLU epilogue
// ---------------------------------------------------------------------------
__global__ void prelu_kernel(float* __restrict__ out, const float* __restrict__ alpha_p) {
    int i = blockIdx.x * blockDim.x + threadIdx.x;
    if (i >= NN * HH / 4) return;
    float alpha = alpha_p[0];
    float4 v = reinterpret_cast<float4*>(out)[i];
    v.x = v.x >= 0.f ? v.x : alpha * v.x;
    v.y = v.y >= 0.f ? v.y : alpha * v.y;
    v.z = v.z >= 0.f ? v.z : alpha * v.z;
    v.w = v.w >= 0.f ? v.w : alpha * v.w;
    reinterpret_cast<float4*>(out)[i] = v;
}

// ---------------------------------------------------------------------------
// kernel_launch — inputs: X, rows, cols, vals, W, b, alpha
// ---------------------------------------------------------------------------
extern "C" void kernel_launch(void* const* d_in, const int* in_sizes, int n_in,
                              void* d_out, int out_size) {
    const float* X     = (const float*)d_in[0];
    const int*   rows  = (const int*)  d_in[1];
    const int*   cols  = (const int*)  d_in[2];
    const float* vals  = (const float*)d_in[3];
    const float* W     = (const float*)d_in[4];
    const float* b     = (const float*)d_in[5];
    const float* alpha = (const float*)d_in[6];
    float* out = (float*)d_out;

    cudaFuncSetAttribute(gemm_kernel, cudaFuncAttributeMaxDynamicSharedMemorySize, SMEM_TOTAL);

    pack_a_kernel<<<(NN * (DD / 4) + 255) / 256, 256>>>(X);
    pack_b_kernel<<<(K1 * DD * HH + 255) / 256, 256>>>(W);

    gemm_kernel<<<dim3(NJ / BN, MTILES), 256, SMEM_TOTAL>>>();

    bias_init_kernel<<<(NN * HH / 4 + 255) / 256, 256>>>(b, out);

    size_t total_threads = (size_t)K1 * EE * 32;
    spmm_kernel<<<(unsigned)((total_threads + 255) / 256), 256>>>(rows, cols, vals, out);

    prelu_kernel<<<(NN * HH / 4 + 255) / 256, 256>>>(out, alpha);
}

// round 6
// speedup vs baseline: 5.4056x; 1.2804x over previous
#include <cuda_runtime.h>
#include <cuda_fp16.h>
#include <cstdint>

// ---------------------------------------------------------------------------
// Problem constants
// ---------------------------------------------------------------------------
#define NN 50000
#define EE 400000
#define K1 4
#define HH 256
#define NJ 1024                 // K1 * HH
#define DD 1280
#define KK 1280
#define KTILES 20               // KK / 64
#define MTILES 391              // ceil(50000 / 128)
#define MPAD (MTILES * 128)
#define NE (K1 * EE)            // 1.6M edges
#define NB (K1 * NN)            // 200000 buckets
#define NSB 196                 // scan blocks: ceil(NB / 1024)

// GEMM tiling
#define BM 128
#define BN 128
#define BK 64
#define STAGE_BYTES 32768
#define NSTAGES 3
#define SMEM_TOTAL (NSTAGES * STAGE_BYTES)   // 96 KB

// ---------------------------------------------------------------------------
// Device scratch
// ---------------------------------------------------------------------------
__device__ __align__(16) __half g_A[(size_t)MPAD * KK];   // 128 MB
__device__ __align__(16) __half g_B[(size_t)NJ * KK];     // 2.6 MB
__device__ float g_Y[(size_t)NN * NJ];                    // 205 MB
__device__ int   g_cnt[NB];
__device__ int   g_off[NB];
__device__ int   g_cur[NB];
__device__ int   g_blk[NSB];
__device__ int2  g_pcv[NE];                               // permuted (col, val)

// ---------------------------------------------------------------------------
// PTX helpers
// ---------------------------------------------------------------------------
__device__ __forceinline__ uint32_t smem_u32(const void* p) {
    uint32_t a;
    asm("{ .reg .u64 t; cvta.to.shared.u64 t, %1; cvt.u32.u64 %0, t; }" : "=r"(a) : "l"(p));
    return a;
}
__device__ __forceinline__ void cp16(uint32_t dst, const void* src) {
    asm volatile("cp.async.cg.shared.global [%0], [%1], 16;" :: "r"(dst), "l"(src));
}
#define CP_COMMIT() asm volatile("cp.async.commit_group;" ::: "memory")
#define CP_WAIT1()  asm volatile("cp.async.wait_group 1;" ::: "memory")

__device__ __forceinline__ void ldsm_x4(uint32_t* d, uint32_t addr) {
    asm volatile("ldmatrix.sync.aligned.m8n8.x4.shared.b16 {%0,%1,%2,%3}, [%4];"
                 : "=r"(d[0]), "=r"(d[1]), "=r"(d[2]), "=r"(d[3]) : "r"(addr));
}
__device__ __forceinline__ void mma16816(float* c, const uint32_t* a, const uint32_t* b) {
    asm volatile(
        "mma.sync.aligned.m16n8k16.row.col.f32.f16.f16.f32 "
        "{%0,%1,%2,%3}, {%4,%5,%6,%7}, {%8,%9}, {%0,%1,%2,%3};"
        : "+f"(c[0]), "+f"(c[1]), "+f"(c[2]), "+f"(c[3])
        : "r"(a[0]), "r"(a[1]), "r"(a[2]), "r"(a[3]), "r"(b[0]), "r"(b[1]));
}

// ---------------------------------------------------------------------------
// Pack A: X fp32 -> g_A fp16 [MPAD, 1280]
// ---------------------------------------------------------------------------
__global__ void pack_a_kernel(const float* __restrict__ X) {
    int idx = blockIdx.x * blockDim.x + threadIdx.x;
    if (idx >= NN * (DD / 4)) return;
    int m = idx / (DD / 4);
    int q = idx % (DD / 4);
    float4 x = reinterpret_cast<const float4*>(X)[(size_t)m * (DD / 4) + q];
    __half2 ha = __halves2half2(__float2half_rn(x.x), __float2half_rn(x.y));
    __half2 hb = __halves2half2(__float2half_rn(x.z), __float2half_rn(x.w));
    uint2 hv;
    hv.x = *reinterpret_cast<uint32_t*>(&ha);
    hv.y = *reinterpret_cast<uint32_t*>(&hb);
    *reinterpret_cast<uint2*>(g_A + (size_t)m * KK + q * 4) = hv;
}

// ---------------------------------------------------------------------------
// Pack B: W fp32 [K1, D, H] -> g_B fp16 [k1*H+h][1280]
// ---------------------------------------------------------------------------
__global__ void pack_b_kernel(const float* __restrict__ W) {
    int idx = blockIdx.x * blockDim.x + threadIdx.x;
    if (idx >= K1 * DD * HH) return;
    int h = idx % HH;
    int d = (idx / HH) % DD;
    int k1 = idx / (HH * DD);
    g_B[(size_t)(k1 * HH + h) * KK + d] = __float2half_rn(W[idx]);
}

// ---------------------------------------------------------------------------
// GEMM (fp16 in, fp32 accum), now 2 CTAs/SM
// ---------------------------------------------------------------------------
__device__ __forceinline__ void issue_stage(int kc, uint32_t sbase, int mt, int nt, int tid) {
    if (kc < KTILES) {
        int kb = kc * BK;
        uint32_t sA = sbase + (uint32_t)(kc % NSTAGES) * STAGE_BYTES;
        uint32_t sB = sA + 16384;
        const __half* Ab = g_A + (size_t)(mt * BM) * KK + kb;
        const __half* Bb = g_B + (size_t)(nt * BN) * KK + kb;
        #pragma unroll
        for (int i = 0; i < 4; i++) {
            int idx = tid + i * 256;
            int row = idx >> 3;
            int c = idx & 7;
            uint32_t sw = (uint32_t)((c * 16) ^ ((row & 7) << 4));
            cp16(sA + row * 128 + sw, Ab + (size_t)row * KK + c * 8);
            cp16(sB + row * 128 + sw, Bb + (size_t)row * KK + c * 8);
        }
    }
    CP_COMMIT();
}

__global__ __launch_bounds__(256, 2) void gemm_kernel() {
    extern __shared__ char smem[];
    uint32_t sbase = smem_u32(smem);
    int tid = threadIdx.x, lane = tid & 31, wid = tid >> 5;
    int nt = blockIdx.x, mt = blockIdx.y;
    int wm = wid >> 2, wn = wid & 3;

    float acc[4][4][4];
    #pragma unroll
    for (int i = 0; i < 4; i++)
        #pragma unroll
        for (int j = 0; j < 4; j++)
            #pragma unroll
            for (int r = 0; r < 4; r++) acc[i][j][r] = 0.0f;

    issue_stage(0, sbase, mt, nt, tid);
    issue_stage(1, sbase, mt, nt, tid);

    int a_r = lane & 15, a_g = lane >> 4;
    int b_g = lane >> 3, b_r = lane & 7;
    int b_nrow_base = wn * 32 + (b_g >> 1) * 8 + b_r;
    int b_csel = b_g & 1;

    for (int kc = 0; kc < KTILES; kc++) {
        CP_WAIT1();
        __syncthreads();
        issue_stage(kc + 2, sbase, mt, nt, tid);

        uint32_t sA = sbase + (uint32_t)(kc % NSTAGES) * STAGE_BYTES;
        uint32_t sB = sA + 16384;

        #pragma unroll
        for (int ks = 0; ks < 4; ks++) {
            uint32_t af[4][4], bf[2][4];
            #pragma unroll
            for (int mi = 0; mi < 4; mi++) {
                int row = wm * 64 + mi * 16 + a_r;
                int col16 = ks * 2 + a_g;
                uint32_t addr = sA + row * 128 + (uint32_t)((col16 * 16) ^ ((row & 7) << 4));
                ldsm_x4(af[mi], addr);
            }
            #pragma unroll
            for (int p = 0; p < 2; p++) {
                int nrow = b_nrow_base + p * 16;
                int col16 = ks * 2 + b_csel;
                uint32_t addr = sB + nrow * 128 + (uint32_t)((col16 * 16) ^ ((nrow & 7) << 4));
                ldsm_x4(bf[p], addr);
            }
            #pragma unroll
            for (int mi = 0; mi < 4; mi++)
                #pragma unroll
                for (int ni = 0; ni < 4; ni++)
                    mma16816(acc[mi][ni], af[mi], &bf[ni >> 1][(ni & 1) * 2]);
        }
    }

    int nbase = nt * BN + wn * 32;
    #pragma unroll
    for (int mi = 0; mi < 4; mi++) {
        int row0 = mt * BM + wm * 64 + mi * 16 + (lane >> 2);
        #pragma unroll
        for (int ni = 0; ni < 4; ni++) {
            int col = nbase + ni * 8 + (lane & 3) * 2;
            if (row0 < NN)
                *reinterpret_cast<float2*>(g_Y + (size_t)row0 * NJ + col) =
                    make_float2(acc[mi][ni][0], acc[mi][ni][1]);
            if (row0 + 8 < NN)
                *reinterpret_cast<float2*>(g_Y + (size_t)(row0 + 8) * NJ + col) =
                    make_float2(acc[mi][ni][2], acc[mi][ni][3]);
        }
    }
}

// ---------------------------------------------------------------------------
// CSR build: zero -> histogram -> 3-pass exclusive scan -> scatter permute
// ---------------------------------------------------------------------------
__global__ void zero_cnt_kernel() {
    int i = blockIdx.x * blockDim.x + threadIdx.x;
    if (i < NB) g_cnt[i] = 0;
}

__global__ void hist_kernel(const int* __restrict__ rows) {
    int gw = blockIdx.x * blockDim.x + threadIdx.x;
    if (gw >= NE) return;
    int bkt = (gw / EE) * NN + rows[gw];
    atomicAdd(&g_cnt[bkt], 1);
}

// exclusive block scan; returns exclusive prefix, total via smem_warp[nw-1]
__device__ __forceinline__ int block_scan_exc(int v, int* sw, int tid, int nwarps) {
    int lane = tid & 31, w = tid >> 5;
    int x = v;
    #pragma unroll
    for (int d = 1; d < 32; d <<= 1) {
        int y = __shfl_up_sync(0xFFFFFFFFu, x, d);
        if (lane >= d) x += y;
    }
    if (lane == 31) sw[w] = x;
    __syncthreads();
    if (w == 0) {
        int s = (lane < nwarps) ? sw[lane] : 0;
        #pragma unroll
        for (int d = 1; d < 32; d <<= 1) {
            int y = __shfl_up_sync(0xFFFFFFFFu, s, d);
            if (lane >= d) s += y;
        }
        if (lane < nwarps) sw[lane] = s;
    }
    __syncthreads();
    int woff = (w == 0) ? 0 : sw[w - 1];
    return woff + x - v;
}

__global__ __launch_bounds__(1024) void scan1_kernel() {
    __shared__ int sw[32];
    int tid = threadIdx.x;
    int idx = blockIdx.x * 1024 + tid;
    int v = (idx < NB) ? g_cnt[idx] : 0;
    int e = block_scan_exc(v, sw, tid, 32);
    if (idx < NB) g_off[idx] = e;
    if (tid == 1023) g_blk[blockIdx.x] = e + v;
}

__global__ __launch_bounds__(256) void scan2_kernel() {
    __shared__ int sw[32];
    int tid = threadIdx.x;
    int v = (tid < NSB) ? g_blk[tid] : 0;
    int e = block_scan_exc(v, sw, tid, 8);
    if (tid < NSB) g_blk[tid] = e;
}

__global__ __launch_bounds__(1024) void scan3_kernel() {
    int tid = threadIdx.x;
    int idx = blockIdx.x * 1024 + tid;
    if (idx < NB) {
        int o = g_off[idx] + g_blk[blockIdx.x];
        g_off[idx] = o;
        g_cur[idx] = o;
    }
}

__global__ void scatter_kernel(const int* __restrict__ rows, const int* __restrict__ cols,
                               const float* __restrict__ vals) {
    int gw = blockIdx.x * blockDim.x + threadIdx.x;
    if (gw >= NE) return;
    int bkt = (gw / EE) * NN + rows[gw];
    int pos = atomicAdd(&g_cur[bkt], 1);
    g_pcv[pos] = make_int2(cols[gw], __float_as_int(vals[gw]));
}

// ---------------------------------------------------------------------------
// Pull SpMM: one warp per dest row, all 4 hops accumulated in registers,
// fused bias + PReLU, single store (no global atomics).
// ---------------------------------------------------------------------------
__global__ __launch_bounds__(256) void spmm_pull_kernel(const float* __restrict__ b,
                                                        const float* __restrict__ alpha_p,
                                                        float* __restrict__ out) {
    __shared__ float bs[HH];
    int tid = threadIdx.x;
    bs[tid] = b[tid] + b[HH + tid] + b[2 * HH + tid] + b[3 * HH + tid];
    __syncthreads();

    int warp = tid >> 5, lane = tid & 31;
    int d = blockIdx.x * 8 + warp;
    if (d >= NN) return;

    float4 a0 = make_float4(0.f, 0.f, 0.f, 0.f);
    float4 a1 = make_float4(0.f, 0.f, 0.f, 0.f);

    #pragma unroll
    for (int k = 0; k < K1; k++) {
        int bkt = k * NN + d;
        int start = g_off[bkt];
        int cnt = g_cnt[bkt];
        for (int j = 0; j < cnt; j++) {
            int2 cv = g_pcv[start + j];
            float v = __int_as_float(cv.y);
            const float4* yp = reinterpret_cast<const float4*>(
                g_Y + (size_t)cv.x * NJ + k * HH);
            float4 y0 = yp[lane];
            float4 y1 = yp[lane + 32];
            a0.x += v * y0.x; a0.y += v * y0.y; a0.z += v * y0.z; a0.w += v * y0.w;
            a1.x += v * y1.x; a1.y += v * y1.y; a1.z += v * y1.z; a1.w += v * y1.w;
        }
    }

    float alpha = alpha_p[0];
    int c0 = lane * 4, c1 = (lane + 32) * 4;
    a0.x += bs[c0 + 0]; a0.y += bs[c0 + 1]; a0.z += bs[c0 + 2]; a0.w += bs[c0 + 3];
    a1.x += bs[c1 + 0]; a1.y += bs[c1 + 1]; a1.z += bs[c1 + 2]; a1.w += bs[c1 + 3];
    a0.x = a0.x >= 0.f ? a0.x : alpha * a0.x;
    a0.y = a0.y >= 0.f ? a0.y : alpha * a0.y;
    a0.z = a0.z >= 0.f ? a0.z : alpha * a0.z;
    a0.w = a0.w >= 0.f ? a0.w : alpha * a0.w;
    a1.x = a1.x >= 0.f ? a1.x : alpha * a1.x;
    a1.y = a1.y >= 0.f ? a1.y : alpha * a1.y;
    a1.z = a1.z >= 0.f ? a1.z : alpha * a1.z;
    a1.w = a1.w >= 0.f ? a1.w : alpha * a1.w;

    float4* op = reinterpret_cast<float4*>(out + (size_t)d * HH);
    op[lane] = a0;
    op[lane + 32] = a1;
}

// ---------------------------------------------------------------------------
// kernel_launch — inputs: X, rows, cols, vals, W, b, alpha
// ---------------------------------------------------------------------------
extern "C" void kernel_launch(void* const* d_in, const int* in_sizes, int n_in,
                              void* d_out, int out_size) {
    const float* X     = (const float*)d_in[0];
    const int*   rows  = (const int*)  d_in[1];
    const int*   cols  = (const int*)  d_in[2];
    const float* vals  = (const float*)d_in[3];
    const float* W     = (const float*)d_in[4];
    const float* b     = (const float*)d_in[5];
    const float* alpha = (const float*)d_in[6];
    float* out = (float*)d_out;

    cudaFuncSetAttribute(gemm_kernel, cudaFuncAttributeMaxDynamicSharedMemorySize, SMEM_TOTAL);

    pack_a_kernel<<<(NN * (DD / 4) + 255) / 256, 256>>>(X);
    pack_b_kernel<<<(K1 * DD * HH + 255) / 256, 256>>>(W);

    gemm_kernel<<<dim3(NJ / BN, MTILES), 256, SMEM_TOTAL>>>();

    // CSR build (runs concurrently-ish with nothing; cheap)
    zero_cnt_kernel<<<(NB + 255) / 256, 256>>>();
    hist_kernel<<<(NE + 255) / 256, 256>>>(rows);
    scan1_kernel<<<NSB, 1024>>>();
    scan2_kernel<<<1, 256>>>();
    scan3_kernel<<<NSB, 1024>>>();
    scatter_kernel<<<(NE + 255) / 256, 256>>>(rows, cols, vals);

    // pull SpMM with fused bias + PReLU
    spmm_pull_kernel<<<(NN + 7) / 8, 256>>>(b, alpha, out);
}

// round 7
// speedup vs baseline: 6.3075x; 1.1668x over previous
#include <cuda_runtime.h>
#include <cuda_fp16.h>
#include <cstdint>

// ---------------------------------------------------------------------------
// Problem constants
// ---------------------------------------------------------------------------
#define NN 50000
#define EE 400000
#define K1 4
#define HH 256
#define NJ 1024                 // K1 * HH
#define DD 1280
#define KK 1280
#define KTILES 20               // KK / 64
#define MTILES 391              // ceil(50000 / 128)
#define MPAD (MTILES * 128)
#define NE (K1 * EE)            // 1.6M edges
#define NB (K1 * NN)            // 200000 buckets
#define NSB 196                 // scan blocks: ceil(NB / 1024)

// GEMM tiling
#define BM 128
#define BN 128
#define BK 64
#define STAGE_BYTES 32768
#define NSTAGES 3
#define SMEM_TOTAL (NSTAGES * STAGE_BYTES)   // 96 KB

// ---------------------------------------------------------------------------
// Device scratch
// ---------------------------------------------------------------------------
__device__ __align__(16) __half g_A[(size_t)MPAD * KK];   // 128 MB
__device__ __align__(16) __half g_B[(size_t)NJ * KK];     // 2.6 MB
__device__ __align__(16) __half g_Y[(size_t)NN * NJ];     // 102 MB (fits L2!)
__device__ int   g_cnt[NB];
__device__ int   g_off[NB];
__device__ int   g_cur[NB];
__device__ int   g_blk[NSB];
__device__ int2  g_pcv[NE];                               // permuted (col, val)

// ---------------------------------------------------------------------------
// PTX helpers
// ---------------------------------------------------------------------------
__device__ __forceinline__ uint32_t smem_u32(const void* p) {
    uint32_t a;
    asm("{ .reg .u64 t; cvta.to.shared.u64 t, %1; cvt.u32.u64 %0, t; }" : "=r"(a) : "l"(p));
    return a;
}
__device__ __forceinline__ void cp16(uint32_t dst, const void* src) {
    asm volatile("cp.async.cg.shared.global [%0], [%1], 16;" :: "r"(dst), "l"(src));
}
#define CP_COMMIT() asm volatile("cp.async.commit_group;" ::: "memory")
#define CP_WAIT1()  asm volatile("cp.async.wait_group 1;" ::: "memory")

__device__ __forceinline__ void ldsm_x4(uint32_t* d, uint32_t addr) {
    asm volatile("ldmatrix.sync.aligned.m8n8.x4.shared.b16 {%0,%1,%2,%3}, [%4];"
                 : "=r"(d[0]), "=r"(d[1]), "=r"(d[2]), "=r"(d[3]) : "r"(addr));
}
__device__ __forceinline__ void mma16816(float* c, const uint32_t* a, const uint32_t* b) {
    asm volatile(
        "mma.sync.aligned.m16n8k16.row.col.f32.f16.f16.f32 "
        "{%0,%1,%2,%3}, {%4,%5,%6,%7}, {%8,%9}, {%0,%1,%2,%3};"
        : "+f"(c[0]), "+f"(c[1]), "+f"(c[2]), "+f"(c[3])
        : "r"(a[0]), "r"(a[1]), "r"(a[2]), "r"(a[3]), "r"(b[0]), "r"(b[1]));
}

// ---------------------------------------------------------------------------
// Pack A: X fp32 -> g_A fp16 [MPAD, 1280]
// ---------------------------------------------------------------------------
__global__ void pack_a_kernel(const float* __restrict__ X) {
    int idx = blockIdx.x * blockDim.x + threadIdx.x;
    if (idx >= NN * (DD / 4)) return;
    int m = idx / (DD / 4);
    int q = idx % (DD / 4);
    float4 x = reinterpret_cast<const float4*>(X)[(size_t)m * (DD / 4) + q];
    __half2 ha = __halves2half2(__float2half_rn(x.x), __float2half_rn(x.y));
    __half2 hb = __halves2half2(__float2half_rn(x.z), __float2half_rn(x.w));
    uint2 hv;
    hv.x = *reinterpret_cast<uint32_t*>(&ha);
    hv.y = *reinterpret_cast<uint32_t*>(&hb);
    *reinterpret_cast<uint2*>(g_A + (size_t)m * KK + q * 4) = hv;
}

// ---------------------------------------------------------------------------
// Pack B: W fp32 [K1, D, H] -> g_B fp16 [k1*H+h][1280]
// ---------------------------------------------------------------------------
__global__ void pack_b_kernel(const float* __restrict__ W) {
    int idx = blockIdx.x * blockDim.x + threadIdx.x;
    if (idx >= K1 * DD * HH) return;
    int h = idx % HH;
    int d = (idx / HH) % DD;
    int k1 = idx / (HH * DD);
    g_B[(size_t)(k1 * HH + h) * KK + d] = __float2half_rn(W[idx]);
}

// ---------------------------------------------------------------------------
// GEMM (fp16 in, fp32 accum, fp16 out), 2 CTAs/SM
// ---------------------------------------------------------------------------
__device__ __forceinline__ void issue_stage(int kc, uint32_t sbase, int mt, int nt, int tid) {
    if (kc < KTILES) {
        int kb = kc * BK;
        uint32_t sA = sbase + (uint32_t)(kc % NSTAGES) * STAGE_BYTES;
        uint32_t sB = sA + 16384;
        const __half* Ab = g_A + (size_t)(mt * BM) * KK + kb;
        const __half* Bb = g_B + (size_t)(nt * BN) * KK + kb;
        #pragma unroll
        for (int i = 0; i < 4; i++) {
            int idx = tid + i * 256;
            int row = idx >> 3;
            int c = idx & 7;
            uint32_t sw = (uint32_t)((c * 16) ^ ((row & 7) << 4));
            cp16(sA + row * 128 + sw, Ab + (size_t)row * KK + c * 8);
            cp16(sB + row * 128 + sw, Bb + (size_t)row * KK + c * 8);
        }
    }
    CP_COMMIT();
}

__global__ __launch_bounds__(256, 2) void gemm_kernel() {
    extern __shared__ char smem[];
    uint32_t sbase = smem_u32(smem);
    int tid = threadIdx.x, lane = tid & 31, wid = tid >> 5;
    int nt = blockIdx.x, mt = blockIdx.y;
    int wm = wid >> 2, wn = wid & 3;

    float acc[4][4][4];
    #pragma unroll
    for (int i = 0; i < 4; i++)
        #pragma unroll
        for (int j = 0; j < 4; j++)
            #pragma unroll
            for (int r = 0; r < 4; r++) acc[i][j][r] = 0.0f;

    issue_stage(0, sbase, mt, nt, tid);
    issue_stage(1, sbase, mt, nt, tid);

    int a_r = lane & 15, a_g = lane >> 4;
    int b_g = lane >> 3, b_r = lane & 7;
    int b_nrow_base = wn * 32 + (b_g >> 1) * 8 + b_r;
    int b_csel = b_g & 1;

    for (int kc = 0; kc < KTILES; kc++) {
        CP_WAIT1();
        __syncthreads();
        issue_stage(kc + 2, sbase, mt, nt, tid);

        uint32_t sA = sbase + (uint32_t)(kc % NSTAGES) * STAGE_BYTES;
        uint32_t sB = sA + 16384;

        #pragma unroll
        for (int ks = 0; ks < 4; ks++) {
            uint32_t af[4][4], bf[2][4];
            #pragma unroll
            for (int mi = 0; mi < 4; mi++) {
                int row = wm * 64 + mi * 16 + a_r;
                int col16 = ks * 2 + a_g;
                uint32_t addr = sA + row * 128 + (uint32_t)((col16 * 16) ^ ((row & 7) << 4));
                ldsm_x4(af[mi], addr);
            }
            #pragma unroll
            for (int p = 0; p < 2; p++) {
                int nrow = b_nrow_base + p * 16;
                int col16 = ks * 2 + b_csel;
                uint32_t addr = sB + nrow * 128 + (uint32_t)((col16 * 16) ^ ((nrow & 7) << 4));
                ldsm_x4(bf[p], addr);
            }
            #pragma unroll
            for (int mi = 0; mi < 4; mi++)
                #pragma unroll
                for (int ni = 0; ni < 4; ni++)
                    mma16816(acc[mi][ni], af[mi], &bf[ni >> 1][(ni & 1) * 2]);
        }
    }

    // epilogue: fp16 stores into g_Y
    int nbase = nt * BN + wn * 32;
    #pragma unroll
    for (int mi = 0; mi < 4; mi++) {
        int row0 = mt * BM + wm * 64 + mi * 16 + (lane >> 2);
        #pragma unroll
        for (int ni = 0; ni < 4; ni++) {
            int col = nbase + ni * 8 + (lane & 3) * 2;
            if (row0 < NN) {
                __half2 h = __halves2half2(__float2half_rn(acc[mi][ni][0]),
                                           __float2half_rn(acc[mi][ni][1]));
                *reinterpret_cast<__half2*>(g_Y + (size_t)row0 * NJ + col) = h;
            }
            if (row0 + 8 < NN) {
                __half2 h = __halves2half2(__float2half_rn(acc[mi][ni][2]),
                                           __float2half_rn(acc[mi][ni][3]));
                *reinterpret_cast<__half2*>(g_Y + (size_t)(row0 + 8) * NJ + col) = h;
            }
        }
    }
}

// ---------------------------------------------------------------------------
// CSR build: zero -> histogram -> 3-pass exclusive scan -> scatter permute
// ---------------------------------------------------------------------------
__global__ void zero_cnt_kernel() {
    int i = blockIdx.x * blockDim.x + threadIdx.x;
    if (i < NB) g_cnt[i] = 0;
}

__global__ void hist_kernel(const int* __restrict__ rows) {
    int gw = blockIdx.x * blockDim.x + threadIdx.x;
    if (gw >= NE) return;
    int bkt = (gw / EE) * NN + rows[gw];
    atomicAdd(&g_cnt[bkt], 1);
}

__device__ __forceinline__ int block_scan_exc(int v, int* sw, int tid, int nwarps) {
    int lane = tid & 31, w = tid >> 5;
    int x = v;
    #pragma unroll
    for (int d = 1; d < 32; d <<= 1) {
        int y = __shfl_up_sync(0xFFFFFFFFu, x, d);
        if (lane >= d) x += y;
    }
    if (lane == 31) sw[w] = x;
    __syncthreads();
    if (w == 0) {
        int s = (lane < nwarps) ? sw[lane] : 0;
        #pragma unroll
        for (int d = 1; d < 32; d <<= 1) {
            int y = __shfl_up_sync(0xFFFFFFFFu, s, d);
            if (lane >= d) s += y;
        }
        if (lane < nwarps) sw[lane] = s;
    }
    __syncthreads();
    int woff = (w == 0) ? 0 : sw[w - 1];
    return woff + x - v;
}

__global__ __launch_bounds__(1024) void scan1_kernel() {
    __shared__ int sw[32];
    int tid = threadIdx.x;
    int idx = blockIdx.x * 1024 + tid;
    int v = (idx < NB) ? g_cnt[idx] : 0;
    int e = block_scan_exc(v, sw, tid, 32);
    if (idx < NB) g_off[idx] = e;
    if (tid == 1023) g_blk[blockIdx.x] = e + v;
}

__global__ __launch_bounds__(256) void scan2_kernel() {
    __shared__ int sw[32];
    int tid = threadIdx.x;
    int v = (tid < NSB) ? g_blk[tid] : 0;
    int e = block_scan_exc(v, sw, tid, 8);
    if (tid < NSB) g_blk[tid] = e;
}

__global__ __launch_bounds__(1024) void scan3_kernel() {
    int tid = threadIdx.x;
    int idx = blockIdx.x * 1024 + tid;
    if (idx < NB) {
        int o = g_off[idx] + g_blk[blockIdx.x];
        g_off[idx] = o;
        g_cur[idx] = o;
    }
}

__global__ void scatter_kernel(const int* __restrict__ rows, const int* __restrict__ cols,
                               const float* __restrict__ vals) {
    int gw = blockIdx.x * blockDim.x + threadIdx.x;
    if (gw >= NE) return;
    int bkt = (gw / EE) * NN + rows[gw];
    int pos = atomicAdd(&g_cur[bkt], 1);
    g_pcv[pos] = make_int2(cols[gw], __float_as_int(vals[gw]));
}

// ---------------------------------------------------------------------------
// Pull SpMM (fp16 gathers, fp32 accum): one warp per dest row, fused bias+PReLU.
// Each lane handles 8 contiguous columns (one uint4 of halves per edge).
// ---------------------------------------------------------------------------
__global__ __launch_bounds__(256) void spmm_pull_kernel(const float* __restrict__ b,
                                                        const float* __restrict__ alpha_p,
                                                        float* __restrict__ out) {
    __shared__ float bs[HH];
    int tid = threadIdx.x;
    bs[tid] = b[tid] + b[HH + tid] + b[2 * HH + tid] + b[3 * HH + tid];
    __syncthreads();

    int warp = tid >> 5, lane = tid & 31;
    int d = blockIdx.x * 8 + warp;
    if (d >= NN) return;

    float a[8];
    #pragma unroll
    for (int j = 0; j < 8; j++) a[j] = 0.0f;

    #pragma unroll
    for (int k = 0; k < K1; k++) {
        int bkt = k * NN + d;
        int start = g_off[bkt];
        int cnt = g_cnt[bkt];
        for (int j = 0; j < cnt; j++) {
            int2 cv = g_pcv[start + j];
            float v = __int_as_float(cv.y);
            const uint4* yp = reinterpret_cast<const uint4*>(
                g_Y + (size_t)cv.x * NJ + k * HH);
            uint4 y = yp[lane];               // 8 halves
            const __half2* h2 = reinterpret_cast<const __half2*>(&y);
            #pragma unroll
            for (int p = 0; p < 4; p++) {
                float2 f = __half22float2(h2[p]);
                a[2 * p + 0] += v * f.x;
                a[2 * p + 1] += v * f.y;
            }
        }
    }

    float alpha = alpha_p[0];
    int c0 = lane * 8;
    #pragma unroll
    for (int j = 0; j < 8; j++) {
        a[j] += bs[c0 + j];
        a[j] = a[j] >= 0.f ? a[j] : alpha * a[j];
    }
    float4* op = reinterpret_cast<float4*>(out + (size_t)d * HH + c0);
    op[0] = make_float4(a[0], a[1], a[2], a[3]);
    op[1] = make_float4(a[4], a[5], a[6], a[7]);
}

// ---------------------------------------------------------------------------
// kernel_launch — inputs: X, rows, cols, vals, W, b, alpha
// ---------------------------------------------------------------------------
extern "C" void kernel_launch(void* const* d_in, const int* in_sizes, int n_in,
                              void* d_out, int out_size) {
    const float* X     = (const float*)d_in[0];
    const int*   rows  = (const int*)  d_in[1];
    const int*   cols  = (const int*)  d_in[2];
    const float* vals  = (const float*)d_in[3];
    const float* W     = (const float*)d_in[4];
    const float* b     = (const float*)d_in[5];
    const float* alpha = (const float*)d_in[6];
    float* out = (float*)d_out;

    cudaFuncSetAttribute(gemm_kernel, cudaFuncAttributeMaxDynamicSharedMemorySize, SMEM_TOTAL);

    pack_a_kernel<<<(NN * (DD / 4) + 255) / 256, 256>>>(X);
    pack_b_kernel<<<(K1 * DD * HH + 255) / 256, 256>>>(W);

    gemm_kernel<<<dim3(NJ / BN, MTILES), 256, SMEM_TOTAL>>>();

    // CSR build
    zero_cnt_kernel<<<(NB + 255) / 256, 256>>>();
    hist_kernel<<<(NE + 255) / 256, 256>>>(rows);
    scan1_kernel<<<NSB, 1024>>>();
    scan2_kernel<<<1, 256>>>();
    scan3_kernel<<<NSB, 1024>>>();
    scatter_kernel<<<(NE + 255) / 256, 256>>>(rows, cols, vals);

    // pull SpMM with fused bias + PReLU
    spmm_pull_kernel<<<(NN + 7) / 8, 256>>>(b, alpha, out);
}

// round 8
// speedup vs baseline: 6.5079x; 1.0318x over previous
#include <cuda_runtime.h>
#include <cuda_fp16.h>
#include <cstdint>

// ---------------------------------------------------------------------------
// Problem constants
// ---------------------------------------------------------------------------
#define NN 50000
#define EE 400000
#define K1 4
#define HH 256
#define NJ 1024                 // K1 * HH
#define DD 1280
#define KK 1280
#define KTILES 20               // KK / 64
#define MTILES 391              // ceil(50000 / 128)
#define MPAD (MTILES * 128)
#define NE (K1 * EE)            // 1.6M edges
#define NB (K1 * NN)            // 200000 buckets
#define NSB 196                 // scan blocks: ceil(NB / 1024)
#define PACKA_WORK (NN * (DD / 4))   // 16,000,000

// GEMM tiling
#define BM 128
#define BN 128
#define BK 64
#define STAGE_BYTES 32768
#define NSTAGES 3
#define SMEM_TOTAL (NSTAGES * STAGE_BYTES)   // 96 KB

// ---------------------------------------------------------------------------
// Device scratch
// ---------------------------------------------------------------------------
__device__ __align__(16) __half g_A[(size_t)MPAD * KK];   // 128 MB
__device__ __align__(16) __half g_B[(size_t)NJ * KK];     // 2.6 MB
__device__ __align__(16) __half g_Y[(size_t)NN * NJ];     // 102 MB (fits L2)
__device__ int   g_cnt[NB];
__device__ int   g_off[NB];
__device__ int   g_cur[NB];
__device__ int   g_blk[NSB];
__device__ int2  g_pcv[NE];                               // permuted (col, val)

// ---------------------------------------------------------------------------
// PTX helpers
// ---------------------------------------------------------------------------
__device__ __forceinline__ uint32_t smem_u32(const void* p) {
    uint32_t a;
    asm("{ .reg .u64 t; cvta.to.shared.u64 t, %1; cvt.u32.u64 %0, t; }" : "=r"(a) : "l"(p));
    return a;
}
__device__ __forceinline__ void cp16(uint32_t dst, const void* src) {
    asm volatile("cp.async.cg.shared.global [%0], [%1], 16;" :: "r"(dst), "l"(src));
}
#define CP_COMMIT() asm volatile("cp.async.commit_group;" ::: "memory")
#define CP_WAIT1()  asm volatile("cp.async.wait_group 1;" ::: "memory")

__device__ __forceinline__ void ldsm_x4(uint32_t* d, uint32_t addr) {
    asm volatile("ldmatrix.sync.aligned.m8n8.x4.shared.b16 {%0,%1,%2,%3}, [%4];"
                 : "=r"(d[0]), "=r"(d[1]), "=r"(d[2]), "=r"(d[3]) : "r"(addr));
}
__device__ __forceinline__ void mma16816(float* c, const uint32_t* a, const uint32_t* b) {
    asm volatile(
        "mma.sync.aligned.m16n8k16.row.col.f32.f16.f16.f32 "
        "{%0,%1,%2,%3}, {%4,%5,%6,%7}, {%8,%9}, {%0,%1,%2,%3};"
        : "+f"(c[0]), "+f"(c[1]), "+f"(c[2]), "+f"(c[3])
        : "r"(a[0]), "r"(a[1]), "r"(a[2]), "r"(a[3]), "r"(b[0]), "r"(b[1]));
}

// ---------------------------------------------------------------------------
// Pack A (+ fold: zero g_cnt in tail blocks)
// ---------------------------------------------------------------------------
__global__ void pack_a_kernel(const float* __restrict__ X) {
    int idx = blockIdx.x * blockDim.x + threadIdx.x;
    if (idx < PACKA_WORK) {
        int m = idx / (DD / 4);
        int q = idx % (DD / 4);
        float4 x = reinterpret_cast<const float4*>(X)[(size_t)m * (DD / 4) + q];
        __half2 ha = __halves2half2(__float2half_rn(x.x), __float2half_rn(x.y));
        __half2 hb = __halves2half2(__float2half_rn(x.z), __float2half_rn(x.w));
        uint2 hv;
        hv.x = *reinterpret_cast<uint32_t*>(&ha);
        hv.y = *reinterpret_cast<uint32_t*>(&hb);
        *reinterpret_cast<uint2*>(g_A + (size_t)m * KK + q * 4) = hv;
    } else {
        int z = idx - PACKA_WORK;
        if (z < NB) g_cnt[z] = 0;
    }
}

// ---------------------------------------------------------------------------
// Pack B: W fp32 [K1, D, H] -> g_B fp16 [k1*H+h][1280]
// ---------------------------------------------------------------------------
__global__ void pack_b_kernel(const float* __restrict__ W) {
    int idx = blockIdx.x * blockDim.x + threadIdx.x;
    if (idx >= K1 * DD * HH) return;
    int h = idx % HH;
    int d = (idx / HH) % DD;
    int k1 = idx / (HH * DD);
    g_B[(size_t)(k1 * HH + h) * KK + d] = __float2half_rn(W[idx]);
}

// ---------------------------------------------------------------------------
// GEMM (fp16 in, fp32 accum, fp16 out), 2 CTAs/SM — unchanged from R7
// ---------------------------------------------------------------------------
__device__ __forceinline__ void issue_stage(int kc, uint32_t sbase, int mt, int nt, int tid) {
    if (kc < KTILES) {
        int kb = kc * BK;
        uint32_t sA = sbase + (uint32_t)(kc % NSTAGES) * STAGE_BYTES;
        uint32_t sB = sA + 16384;
        const __half* Ab = g_A + (size_t)(mt * BM) * KK + kb;
        const __half* Bb = g_B + (size_t)(nt * BN) * KK + kb;
        #pragma unroll
        for (int i = 0; i < 4; i++) {
            int idx = tid + i * 256;
            int row = idx >> 3;
            int c = idx & 7;
            uint32_t sw = (uint32_t)((c * 16) ^ ((row & 7) << 4));
            cp16(sA + row * 128 + sw, Ab + (size_t)row * KK + c * 8);
            cp16(sB + row * 128 + sw, Bb + (size_t)row * KK + c * 8);
        }
    }
    CP_COMMIT();
}

__global__ __launch_bounds__(256, 2) void gemm_kernel() {
    extern __shared__ char smem[];
    uint32_t sbase = smem_u32(smem);
    int tid = threadIdx.x, lane = tid & 31, wid = tid >> 5;
    int nt = blockIdx.x, mt = blockIdx.y;
    int wm = wid >> 2, wn = wid & 3;

    float acc[4][4][4];
    #pragma unroll
    for (int i = 0; i < 4; i++)
        #pragma unroll
        for (int j = 0; j < 4; j++)
            #pragma unroll
            for (int r = 0; r < 4; r++) acc[i][j][r] = 0.0f;

    issue_stage(0, sbase, mt, nt, tid);
    issue_stage(1, sbase, mt, nt, tid);

    int a_r = lane & 15, a_g = lane >> 4;
    int b_g = lane >> 3, b_r = lane & 7;
    int b_nrow_base = wn * 32 + (b_g >> 1) * 8 + b_r;
    int b_csel = b_g & 1;

    for (int kc = 0; kc < KTILES; kc++) {
        CP_WAIT1();
        __syncthreads();
        issue_stage(kc + 2, sbase, mt, nt, tid);

        uint32_t sA = sbase + (uint32_t)(kc % NSTAGES) * STAGE_BYTES;
        uint32_t sB = sA + 16384;

        #pragma unroll
        for (int ks = 0; ks < 4; ks++) {
            uint32_t af[4][4], bf[2][4];
            #pragma unroll
            for (int mi = 0; mi < 4; mi++) {
                int row = wm * 64 + mi * 16 + a_r;
                int col16 = ks * 2 + a_g;
                uint32_t addr = sA + row * 128 + (uint32_t)((col16 * 16) ^ ((row & 7) << 4));
                ldsm_x4(af[mi], addr);
            }
            #pragma unroll
            for (int p = 0; p < 2; p++) {
                int nrow = b_nrow_base + p * 16;
                int col16 = ks * 2 + b_csel;
                uint32_t addr = sB + nrow * 128 + (uint32_t)((col16 * 16) ^ ((nrow & 7) << 4));
                ldsm_x4(bf[p], addr);
            }
            #pragma unroll
            for (int mi = 0; mi < 4; mi++)
                #pragma unroll
                for (int ni = 0; ni < 4; ni++)
                    mma16816(acc[mi][ni], af[mi], &bf[ni >> 1][(ni & 1) * 2]);
        }
    }

    int nbase = nt * BN + wn * 32;
    #pragma unroll
    for (int mi = 0; mi < 4; mi++) {
        int row0 = mt * BM + wm * 64 + mi * 16 + (lane >> 2);
        #pragma unroll
        for (int ni = 0; ni < 4; ni++) {
            int col = nbase + ni * 8 + (lane & 3) * 2;
            if (row0 < NN) {
                __half2 h = __halves2half2(__float2half_rn(acc[mi][ni][0]),
                                           __float2half_rn(acc[mi][ni][1]));
                *reinterpret_cast<__half2*>(g_Y + (size_t)row0 * NJ + col) = h;
            }
            if (row0 + 8 < NN) {
                __half2 h = __halves2half2(__float2half_rn(acc[mi][ni][2]),
                                           __float2half_rn(acc[mi][ni][3]));
                *reinterpret_cast<__half2*>(g_Y + (size_t)(row0 + 8) * NJ + col) = h;
            }
        }
    }
}

// ---------------------------------------------------------------------------
// CSR build: histogram -> 3-pass exclusive scan -> scatter permute
// ---------------------------------------------------------------------------
__global__ void hist_kernel(const int* __restrict__ rows) {
    int gw = blockIdx.x * blockDim.x + threadIdx.x;
    if (gw >= NE) return;
    int bkt = (gw / EE) * NN + rows[gw];
    atomicAdd(&g_cnt[bkt], 1);
}

__device__ __forceinline__ int block_scan_exc(int v, int* sw, int tid, int nwarps) {
    int lane = tid & 31, w = tid >> 5;
    int x = v;
    #pragma unroll
    for (int d = 1; d < 32; d <<= 1) {
        int y = __shfl_up_sync(0xFFFFFFFFu, x, d);
        if (lane >= d) x += y;
    }
    if (lane == 31) sw[w] = x;
    __syncthreads();
    if (w == 0) {
        int s = (lane < nwarps) ? sw[lane] : 0;
        #pragma unroll
        for (int d = 1; d < 32; d <<= 1) {
            int y = __shfl_up_sync(0xFFFFFFFFu, s, d);
            if (lane >= d) s += y;
        }
        if (lane < nwarps) sw[lane] = s;
    }
    __syncthreads();
    int woff = (w == 0) ? 0 : sw[w - 1];
    return woff + x - v;
}

__global__ __launch_bounds__(1024) void scan1_kernel() {
    __shared__ int sw[32];
    int tid = threadIdx.x;
    int idx = blockIdx.x * 1024 + tid;
    int v = (idx < NB) ? g_cnt[idx] : 0;
    int e = block_scan_exc(v, sw, tid, 32);
    if (idx < NB) g_off[idx] = e;
    if (tid == 1023) g_blk[blockIdx.x] = e + v;
}

__global__ __launch_bounds__(256) void scan2_kernel() {
    __shared__ int sw[32];
    int tid = threadIdx.x;
    int v = (tid < NSB) ? g_blk[tid] : 0;
    int e = block_scan_exc(v, sw, tid, 8);
    if (tid < NSB) g_blk[tid] = e;
}

__global__ __launch_bounds__(1024) void scan3_kernel() {
    int tid = threadIdx.x;
    int idx = blockIdx.x * 1024 + tid;
    if (idx < NB) {
        int o = g_off[idx] + g_blk[blockIdx.x];
        g_off[idx] = o;
        g_cur[idx] = o;
    }
}

__global__ void scatter_kernel(const int* __restrict__ rows, const int* __restrict__ cols,
                               const float* __restrict__ vals) {
    int gw = blockIdx.x * blockDim.x + threadIdx.x;
    if (gw >= NE) return;
    int bkt = (gw / EE) * NN + rows[gw];
    int pos = atomicAdd(&g_cur[bkt], 1);
    g_pcv[pos] = make_int2(cols[gw], __float_as_int(vals[gw]));
}

// ---------------------------------------------------------------------------
// Pull SpMM (fp16 gathers, fp32 accum): one warp per dest row.
// Edge-quad software pipeline: 4 independent cv loads + 4 independent gathers
// in flight per warp iteration (MLP=4). Accumulation order preserved.
// ---------------------------------------------------------------------------
__device__ __forceinline__ void accum_edge(float* a, int2 cv, int k, int lane) {
    float v = __int_as_float(cv.y);
    const uint4* yp = reinterpret_cast<const uint4*>(g_Y + (size_t)cv.x * NJ + k * HH);
    uint4 y = yp[lane];
    const __half2* h2 = reinterpret_cast<const __half2*>(&y);
    #pragma unroll
    for (int p = 0; p < 4; p++) {
        float2 f = __half22float2(h2[p]);
        a[2 * p + 0] += v * f.x;
        a[2 * p + 1] += v * f.y;
    }
}

__global__ __launch_bounds__(256) void spmm_pull_kernel(const float* __restrict__ b,
                                                        const float* __restrict__ alpha_p,
                                                        float* __restrict__ out) {
    __shared__ float bs[HH];
    int tid = threadIdx.x;
    bs[tid] = b[tid] + b[HH + tid] + b[2 * HH + tid] + b[3 * HH + tid];
    __syncthreads();

    int warp = tid >> 5, lane = tid & 31;
    int d = blockIdx.x * 8 + warp;
    if (d >= NN) return;

    float a[8];
    #pragma unroll
    for (int j = 0; j < 8; j++) a[j] = 0.0f;

    #pragma unroll
    for (int k = 0; k < K1; k++) {
        int bkt = k * NN + d;
        int start = g_off[bkt];
        int cnt = g_cnt[bkt];
        int j = 0;
        for (; j + 4 <= cnt; j += 4) {
            // 4 independent cv loads, then 4 independent 512B gathers (MLP=4)
            int2 cv0 = g_pcv[start + j + 0];
            int2 cv1 = g_pcv[start + j + 1];
            int2 cv2 = g_pcv[start + j + 2];
            int2 cv3 = g_pcv[start + j + 3];
            const uint4* y0p = reinterpret_cast<const uint4*>(g_Y + (size_t)cv0.x * NJ + k * HH);
            const uint4* y1p = reinterpret_cast<const uint4*>(g_Y + (size_t)cv1.x * NJ + k * HH);
            const uint4* y2p = reinterpret_cast<const uint4*>(g_Y + (size_t)cv2.x * NJ + k * HH);
            const uint4* y3p = reinterpret_cast<const uint4*>(g_Y + (size_t)cv3.x * NJ + k * HH);
            uint4 y0 = y0p[lane];
            uint4 y1 = y1p[lane];
            uint4 y2 = y2p[lane];
            uint4 y3 = y3p[lane];
            float v0 = __int_as_float(cv0.y), v1 = __int_as_float(cv1.y);
            float v2 = __int_as_float(cv2.y), v3 = __int_as_float(cv3.y);
            const __half2* h0 = reinterpret_cast<const __half2*>(&y0);
            const __half2* h1 = reinterpret_cast<const __half2*>(&y1);
            const __half2* h2 = reinterpret_cast<const __half2*>(&y2);
            const __half2* h3 = reinterpret_cast<const __half2*>(&y3);
            #pragma unroll
            for (int p = 0; p < 4; p++) {
                float2 f0 = __half22float2(h0[p]);
                a[2 * p + 0] += v0 * f0.x; a[2 * p + 1] += v0 * f0.y;
            }
            #pragma unroll
            for (int p = 0; p < 4; p++) {
                float2 f1 = __half22float2(h1[p]);
                a[2 * p + 0] += v1 * f1.x; a[2 * p + 1] += v1 * f1.y;
            }
            #pragma unroll
            for (int p = 0; p < 4; p++) {
                float2 f2 = __half22float2(h2[p]);
                a[2 * p + 0] += v2 * f2.x; a[2 * p + 1] += v2 * f2.y;
            }
            #pragma unroll
            for (int p = 0; p < 4; p++) {
                float2 f3 = __half22float2(h3[p]);
                a[2 * p + 0] += v3 * f3.x; a[2 * p + 1] += v3 * f3.y;
            }
        }
        for (; j < cnt; j++)
            accum_edge(a, g_pcv[start + j], k, lane);
    }

    float alpha = alpha_p[0];
    int c0 = lane * 8;
    #pragma unroll
    for (int j = 0; j < 8; j++) {
        a[j] += bs[c0 + j];
        a[j] = a[j] >= 0.f ? a[j] : alpha * a[j];
    }
    float4* op = reinterpret_cast<float4*>(out + (size_t)d * HH + c0);
    op[0] = make_float4(a[0], a[1], a[2], a[3]);
    op[1] = make_float4(a[4], a[5], a[6], a[7]);
}

// ---------------------------------------------------------------------------
// kernel_launch — inputs: X, rows, cols, vals, W, b, alpha
// ---------------------------------------------------------------------------
extern "C" void kernel_launch(void* const* d_in, const int* in_sizes, int n_in,
                              void* d_out, int out_size) {
    const float* X     = (const float*)d_in[0];
    const int*   rows  = (const int*)  d_in[1];
    const int*   cols  = (const int*)  d_in[2];
    const float* vals  = (const float*)d_in[3];
    const float* W     = (const float*)d_in[4];
    const float* b     = (const float*)d_in[5];
    const float* alpha = (const float*)d_in[6];
    float* out = (float*)d_out;

    cudaFuncSetAttribute(gemm_kernel, cudaFuncAttributeMaxDynamicSharedMemorySize, SMEM_TOTAL);

    // pack A (+ zero g_cnt in tail blocks), pack B
    pack_a_kernel<<<(PACKA_WORK + NB + 255) / 256, 256>>>(X);
    pack_b_kernel<<<(K1 * DD * HH + 255) / 256, 256>>>(W);

    gemm_kernel<<<dim3(NJ / BN, MTILES), 256, SMEM_TOTAL>>>();

    // CSR build
    hist_kernel<<<(NE + 255) / 256, 256>>>(rows);
    scan1_kernel<<<NSB, 1024>>>();
    scan2_kernel<<<1, 256>>>();
    scan3_kernel<<<NSB, 1024>>>();
    scatter_kernel<<<(NE + 255) / 256, 256>>>(rows, cols, vals);

    // pull SpMM with fused bias + PReLU
    spmm_pull_kernel<<<(NN + 7) / 8, 256>>>(b, alpha, out);
}

// round 9
// speedup vs baseline: 6.7758x; 1.0412x over previous
#include <cuda_runtime.h>
#include <cuda_fp16.h>
#include <cstdint>

// ---------------------------------------------------------------------------
// Problem constants
// ---------------------------------------------------------------------------
#define NN 50000
#define EE 400000
#define K1 4
#define HH 256
#define NJ 1024                 // K1 * HH
#define DD 1280
#define KK 1280
#define KTILES 20               // KK / 64
#define MTILES 391              // ceil(50000 / 128)
#define MPAD (MTILES * 128)
#define NE (K1 * EE)            // 1.6M edges
#define NSB 49                  // scan blocks: ceil(NN / 1024)
#define PACKA_WORK (NN * (DD / 4))

// GEMM tiling
#define BM 128
#define BN 128
#define BK 64
#define STAGE_BYTES 32768
#define NSTAGES 3
#define SMEM_TOTAL (NSTAGES * STAGE_BYTES)   // 96 KB

// ---------------------------------------------------------------------------
// Device scratch
// ---------------------------------------------------------------------------
__device__ __align__(16) __half g_A[(size_t)MPAD * KK];   // 128 MB
__device__ __align__(16) __half g_B[(size_t)NJ * KK];     // 2.6 MB
__device__ __align__(16) __half g_Y[(size_t)NN * NJ];     // 102 MB (fits L2)
__device__ int   g_cnt[NN];
__device__ int   g_off[NN];
__device__ int   g_cur[NN];
__device__ int   g_blk[NSB];
__device__ int2  g_pcv[NE];     // (precomputed half-offset into g_Y, val bits)

// ---------------------------------------------------------------------------
// PTX helpers
// ---------------------------------------------------------------------------
__device__ __forceinline__ uint32_t smem_u32(const void* p) {
    uint32_t a;
    asm("{ .reg .u64 t; cvta.to.shared.u64 t, %1; cvt.u32.u64 %0, t; }" : "=r"(a) : "l"(p));
    return a;
}
__device__ __forceinline__ void cp16(uint32_t dst, const void* src) {
    asm volatile("cp.async.cg.shared.global [%0], [%1], 16;" :: "r"(dst), "l"(src));
}
#define CP_COMMIT() asm volatile("cp.async.commit_group;" ::: "memory")
#define CP_WAIT1()  asm volatile("cp.async.wait_group 1;" ::: "memory")

__device__ __forceinline__ void ldsm_x4(uint32_t* d, uint32_t addr) {
    asm volatile("ldmatrix.sync.aligned.m8n8.x4.shared.b16 {%0,%1,%2,%3}, [%4];"
                 : "=r"(d[0]), "=r"(d[1]), "=r"(d[2]), "=r"(d[3]) : "r"(addr));
}
__device__ __forceinline__ void mma16816(float* c, const uint32_t* a, const uint32_t* b) {
    asm volatile(
        "mma.sync.aligned.m16n8k16.row.col.f32.f16.f16.f32 "
        "{%0,%1,%2,%3}, {%4,%5,%6,%7}, {%8,%9}, {%0,%1,%2,%3};"
        : "+f"(c[0]), "+f"(c[1]), "+f"(c[2]), "+f"(c[3])
        : "r"(a[0]), "r"(a[1]), "r"(a[2]), "r"(a[3]), "r"(b[0]), "r"(b[1]));
}

// ---------------------------------------------------------------------------
// Pack A: X fp32 -> g_A fp16
// ---------------------------------------------------------------------------
__global__ void pack_a_kernel(const float* __restrict__ X) {
    int idx = blockIdx.x * blockDim.x + threadIdx.x;
    if (idx >= PACKA_WORK) return;
    int m = idx / (DD / 4);
    int q = idx % (DD / 4);
    float4 x = reinterpret_cast<const float4*>(X)[(size_t)m * (DD / 4) + q];
    __half2 ha = __halves2half2(__float2half_rn(x.x), __float2half_rn(x.y));
    __half2 hb = __halves2half2(__float2half_rn(x.z), __float2half_rn(x.w));
    uint2 hv;
    hv.x = *reinterpret_cast<uint32_t*>(&ha);
    hv.y = *reinterpret_cast<uint32_t*>(&hb);
    *reinterpret_cast<uint2*>(g_A + (size_t)m * KK + q * 4) = hv;
}

// ---------------------------------------------------------------------------
// Pack B: W fp32 [K1, D, H] -> g_B fp16 [k1*H+h][1280]
// ---------------------------------------------------------------------------
__global__ void pack_b_kernel(const float* __restrict__ W) {
    int idx = blockIdx.x * blockDim.x + threadIdx.x;
    if (idx >= K1 * DD * HH) return;
    int h = idx % HH;
    int d = (idx / HH) % DD;
    int k1 = idx / (HH * DD);
    g_B[(size_t)(k1 * HH + h) * KK + d] = __float2half_rn(W[idx]);
}

// ---------------------------------------------------------------------------
// GEMM (fp16 in, fp32 accum, fp16 out), 2 CTAs/SM — unchanged
// ---------------------------------------------------------------------------
__device__ __forceinline__ void issue_stage(int kc, uint32_t sbase, int mt, int nt, int tid) {
    if (kc < KTILES) {
        int kb = kc * BK;
        uint32_t sA = sbase + (uint32_t)(kc % NSTAGES) * STAGE_BYTES;
        uint32_t sB = sA + 16384;
        const __half* Ab = g_A + (size_t)(mt * BM) * KK + kb;
        const __half* Bb = g_B + (size_t)(nt * BN) * KK + kb;
        #pragma unroll
        for (int i = 0; i < 4; i++) {
            int idx = tid + i * 256;
            int row = idx >> 3;
            int c = idx & 7;
            uint32_t sw = (uint32_t)((c * 16) ^ ((row & 7) << 4));
            cp16(sA + row * 128 + sw, Ab + (size_t)row * KK + c * 8);
            cp16(sB + row * 128 + sw, Bb + (size_t)row * KK + c * 8);
        }
    }
    CP_COMMIT();
}

__global__ __launch_bounds__(256, 2) void gemm_kernel() {
    extern __shared__ char smem[];
    uint32_t sbase = smem_u32(smem);
    int tid = threadIdx.x, lane = tid & 31, wid = tid >> 5;
    int nt = blockIdx.x, mt = blockIdx.y;
    int wm = wid >> 2, wn = wid & 3;

    float acc[4][4][4];
    #pragma unroll
    for (int i = 0; i < 4; i++)
        #pragma unroll
        for (int j = 0; j < 4; j++)
            #pragma unroll
            for (int r = 0; r < 4; r++) acc[i][j][r] = 0.0f;

    issue_stage(0, sbase, mt, nt, tid);
    issue_stage(1, sbase, mt, nt, tid);

    int a_r = lane & 15, a_g = lane >> 4;
    int b_g = lane >> 3, b_r = lane & 7;
    int b_nrow_base = wn * 32 + (b_g >> 1) * 8 + b_r;
    int b_csel = b_g & 1;

    for (int kc = 0; kc < KTILES; kc++) {
        CP_WAIT1();
        __syncthreads();
        issue_stage(kc + 2, sbase, mt, nt, tid);

        uint32_t sA = sbase + (uint32_t)(kc % NSTAGES) * STAGE_BYTES;
        uint32_t sB = sA + 16384;

        #pragma unroll
        for (int ks = 0; ks < 4; ks++) {
            uint32_t af[4][4], bf[2][4];
            #pragma unroll
            for (int mi = 0; mi < 4; mi++) {
                int row = wm * 64 + mi * 16 + a_r;
                int col16 = ks * 2 + a_g;
                uint32_t addr = sA + row * 128 + (uint32_t)((col16 * 16) ^ ((row & 7) << 4));
                ldsm_x4(af[mi], addr);
            }
            #pragma unroll
            for (int p = 0; p < 2; p++) {
                int nrow = b_nrow_base + p * 16;
                int col16 = ks * 2 + b_csel;
                uint32_t addr = sB + nrow * 128 + (uint32_t)((col16 * 16) ^ ((nrow & 7) << 4));
                ldsm_x4(bf[p], addr);
            }
            #pragma unroll
            for (int mi = 0; mi < 4; mi++)
                #pragma unroll
                for (int ni = 0; ni < 4; ni++)
                    mma16816(acc[mi][ni], af[mi], &bf[ni >> 1][(ni & 1) * 2]);
        }
    }

    int nbase = nt * BN + wn * 32;
    #pragma unroll
    for (int mi = 0; mi < 4; mi++) {
        int row0 = mt * BM + wm * 64 + mi * 16 + (lane >> 2);
        #pragma unroll
        for (int ni = 0; ni < 4; ni++) {
            int col = nbase + ni * 8 + (lane & 3) * 2;
            if (row0 < NN) {
                __half2 h = __halves2half2(__float2half_rn(acc[mi][ni][0]),
                                           __float2half_rn(acc[mi][ni][1]));
                *reinterpret_cast<__half2*>(g_Y + (size_t)row0 * NJ + col) = h;
            }
            if (row0 + 8 < NN) {
                __half2 h = __halves2half2(__float2half_rn(acc[mi][ni][2]),
                                           __float2half_rn(acc[mi][ni][3]));
                *reinterpret_cast<__half2*>(g_Y + (size_t)(row0 + 8) * NJ + col) = h;
            }
        }
    }
}

// ---------------------------------------------------------------------------
// CSR build (d-only buckets): zero -> hist -> scan -> scatter
// Scatter stores the PRECOMPUTED half-element offset into g_Y: col*1024 + k*256
// ---------------------------------------------------------------------------
__global__ void zero_cnt_kernel() {
    int i = blockIdx.x * blockDim.x + threadIdx.x;
    if (i < NN) g_cnt[i] = 0;
}

__global__ void hist_kernel(const int* __restrict__ rows) {
    int gw = blockIdx.x * blockDim.x + threadIdx.x;
    if (gw >= NE) return;
    atomicAdd(&g_cnt[rows[gw]], 1);
}

__device__ __forceinline__ int block_scan_exc(int v, int* sw, int tid, int nwarps) {
    int lane = tid & 31, w = tid >> 5;
    int x = v;
    #pragma unroll
    for (int d = 1; d < 32; d <<= 1) {
        int y = __shfl_up_sync(0xFFFFFFFFu, x, d);
        if (lane >= d) x += y;
    }
    if (lane == 31) sw[w] = x;
    __syncthreads();
    if (w == 0) {
        int s = (lane < nwarps) ? sw[lane] : 0;
        #pragma unroll
        for (int d = 1; d < 32; d <<= 1) {
            int y = __shfl_up_sync(0xFFFFFFFFu, s, d);
            if (lane >= d) s += y;
        }
        if (lane < nwarps) sw[lane] = s;
    }
    __syncthreads();
    int woff = (w == 0) ? 0 : sw[w - 1];
    return woff + x - v;
}

__global__ __launch_bounds__(1024) void scan1_kernel() {
    __shared__ int sw[32];
    int tid = threadIdx.x;
    int idx = blockIdx.x * 1024 + tid;
    int v = (idx < NN) ? g_cnt[idx] : 0;
    int e = block_scan_exc(v, sw, tid, 32);
    if (idx < NN) g_off[idx] = e;
    if (tid == 1023) g_blk[blockIdx.x] = e + v;
}

__global__ __launch_bounds__(256) void scan2_kernel() {
    __shared__ int sw[32];
    int tid = threadIdx.x;
    int v = (tid < NSB) ? g_blk[tid] : 0;
    int e = block_scan_exc(v, sw, tid, 8);
    if (tid < NSB) g_blk[tid] = e;
}

__global__ __launch_bounds__(1024) void scan3_kernel() {
    int tid = threadIdx.x;
    int idx = blockIdx.x * 1024 + tid;
    if (idx < NN) {
        int o = g_off[idx] + g_blk[blockIdx.x];
        g_off[idx] = o;
        g_cur[idx] = o;
    }
}

__global__ void scatter_kernel(const int* __restrict__ rows, const int* __restrict__ cols,
                               const float* __restrict__ vals) {
    int gw = blockIdx.x * blockDim.x + threadIdx.x;
    if (gw >= NE) return;
    int k = gw / EE;
    int pos = atomicAdd(&g_cur[rows[gw]], 1);
    int key = cols[gw] * NJ + k * HH;   // direct half-offset into g_Y
    g_pcv[pos] = make_int2(key, __float_as_int(vals[gw]));
}

// ---------------------------------------------------------------------------
// Pull SpMM (fp16 gathers, fp32 accum): one warp per dest row, quad-pipelined
// single run over ~32 edges (all hops merged), fused bias + PReLU.
// ---------------------------------------------------------------------------
__global__ __launch_bounds__(256) void spmm_pull_kernel(const float* __restrict__ b,
                                                        const float* __restrict__ alpha_p,
                                                        float* __restrict__ out) {
    __shared__ float bs[HH];
    int tid = threadIdx.x;
    bs[tid] = b[tid] + b[HH + tid] + b[2 * HH + tid] + b[3 * HH + tid];
    __syncthreads();

    int warp = tid >> 5, lane = tid & 31;
    int d = blockIdx.x * 8 + warp;
    if (d >= NN) return;

    float a[8];
    #pragma unroll
    for (int j = 0; j < 8; j++) a[j] = 0.0f;

    int start = g_off[d];
    int cnt = g_cnt[d];
    int j = 0;
    for (; j + 4 <= cnt; j += 4) {
        int2 cv0 = g_pcv[start + j + 0];
        int2 cv1 = g_pcv[start + j + 1];
        int2 cv2 = g_pcv[start + j + 2];
        int2 cv3 = g_pcv[start + j + 3];
        uint4 y0 = reinterpret_cast<const uint4*>(g_Y + cv0.x)[lane];
        uint4 y1 = reinterpret_cast<const uint4*>(g_Y + cv1.x)[lane];
        uint4 y2 = reinterpret_cast<const uint4*>(g_Y + cv2.x)[lane];
        uint4 y3 = reinterpret_cast<const uint4*>(g_Y + cv3.x)[lane];
        float v0 = __int_as_float(cv0.y), v1 = __int_as_float(cv1.y);
        float v2 = __int_as_float(cv2.y), v3 = __int_as_float(cv3.y);
        const __half2* h0 = reinterpret_cast<const __half2*>(&y0);
        const __half2* h1 = reinterpret_cast<const __half2*>(&y1);
        const __half2* h2 = reinterpret_cast<const __half2*>(&y2);
        const __half2* h3 = reinterpret_cast<const __half2*>(&y3);
        #pragma unroll
        for (int p = 0; p < 4; p++) {
            float2 f = __half22float2(h0[p]);
            a[2 * p + 0] += v0 * f.x; a[2 * p + 1] += v0 * f.y;
        }
        #pragma unroll
        for (int p = 0; p < 4; p++) {
            float2 f = __half22float2(h1[p]);
            a[2 * p + 0] += v1 * f.x; a[2 * p + 1] += v1 * f.y;
        }
        #pragma unroll
        for (int p = 0; p < 4; p++) {
            float2 f = __half22float2(h2[p]);
            a[2 * p + 0] += v2 * f.x; a[2 * p + 1] += v2 * f.y;
        }
        #pragma unroll
        for (int p = 0; p < 4; p++) {
            float2 f = __half22float2(h3[p]);
            a[2 * p + 0] += v3 * f.x; a[2 * p + 1] += v3 * f.y;
        }
    }
    for (; j < cnt; j++) {
        int2 cv = g_pcv[start + j];
        float v = __int_as_float(cv.y);
        uint4 y = reinterpret_cast<const uint4*>(g_Y + cv.x)[lane];
        const __half2* h2 = reinterpret_cast<const __half2*>(&y);
        #pragma unroll
        for (int p = 0; p < 4; p++) {
            float2 f = __half22float2(h2[p]);
            a[2 * p + 0] += v * f.x; a[2 * p + 1] += v * f.y;
        }
    }

    float alpha = alpha_p[0];
    int c0 = lane * 8;
    #pragma unroll
    for (int jj = 0; jj < 8; jj++) {
        a[jj] += bs[c0 + jj];
        a[jj] = a[jj] >= 0.f ? a[jj] : alpha * a[jj];
    }
    float4* op = reinterpret_cast<float4*>(out + (size_t)d * HH + c0);
    op[0] = make_float4(a[0], a[1], a[2], a[3]);
    op[1] = make_float4(a[4], a[5], a[6], a[7]);
}

// ---------------------------------------------------------------------------
// kernel_launch — inputs: X, rows, cols, vals, W, b, alpha
// Two-stream capture: CSR build overlaps packs + GEMM.
// ---------------------------------------------------------------------------
static cudaStream_t make_stream() {
    cudaStream_t s;
    cudaStreamCreateWithFlags(&s, cudaStreamNonBlocking);
    return s;
}
static cudaEvent_t make_event() {
    cudaEvent_t e;
    cudaEventCreateWithFlags(&e, cudaEventDisableTiming);
    return e;
}

extern "C" void kernel_launch(void* const* d_in, const int* in_sizes, int n_in,
                              void* d_out, int out_size) {
    const float* X     = (const float*)d_in[0];
    const int*   rows  = (const int*)  d_in[1];
    const int*   cols  = (const int*)  d_in[2];
    const float* vals  = (const float*)d_in[3];
    const float* W     = (const float*)d_in[4];
    const float* b     = (const float*)d_in[5];
    const float* alpha = (const float*)d_in[6];
    float* out = (float*)d_out;

    static cudaStream_t s2 = make_stream();
    static cudaEvent_t e_fork = make_event();
    static cudaEvent_t e_join = make_event();

    cudaFuncSetAttribute(gemm_kernel, cudaFuncAttributeMaxDynamicSharedMemorySize, SMEM_TOTAL);

    // fork: CSR build on s2 (independent of packs/GEMM)
    cudaEventRecord(e_fork, 0);
    cudaStreamWaitEvent(s2, e_fork, 0);
    zero_cnt_kernel<<<(NN + 255) / 256, 256, 0, s2>>>();
    hist_kernel<<<(NE + 255) / 256, 256, 0, s2>>>(rows);
    scan1_kernel<<<NSB, 1024, 0, s2>>>();
    scan2_kernel<<<1, 256, 0, s2>>>();
    scan3_kernel<<<NSB, 1024, 0, s2>>>();
    scatter_kernel<<<(NE + 255) / 256, 256, 0, s2>>>(rows, cols, vals);
    cudaEventRecord(e_join, s2);

    // main stream: packs + GEMM
    pack_a_kernel<<<(PACKA_WORK + 255) / 256, 256>>>(X);
    pack_b_kernel<<<(K1 * DD * HH + 255) / 256, 256>>>(W);
    gemm_kernel<<<dim3(NJ / BN, MTILES), 256, SMEM_TOTAL>>>();

    // join, then pull SpMM with fused bias + PReLU
    cudaStreamWaitEvent(0, e_join, 0);
    spmm_pull_kernel<<<(NN + 7) / 8, 256>>>(b, alpha, out);
}